// round 1
// baseline (speedup 1.0000x reference)
#include <cuda_runtime.h>
#include <math.h>

#define BB 64
#define PP 196
#define HH 512
#define EE 512
#define AA 512
#define VV 10000
#define MAXCAP 50
#define TT 49
#define NG 2048   // 4*H

// output layout (float32, tuple flattened):
// scores (B,T,V), caps_s (B,50), decode_lengths (B,), weights (B,T,P), sort_ind (B,)
#define N_SCORES   (BB*TT*VV)                 // 31,360,000
#define OFF_CAPS   (N_SCORES)
#define OFF_DECLEN (OFF_CAPS + BB*MAXCAP)
#define OFF_WEIGHTS (OFF_DECLEN + BB)
#define OFF_SORT   (OFF_WEIGHTS + BB*TT*PP)

// ---------------- scratch (device globals; zero-initialized at load) ----------------
__device__ float g_feats[BB*PP*HH];     // sorted image features
__device__ float g_encatt[BB*PP*AA];    // feats @ W_enc^T + b_enc
__device__ float g_embT[BB*TT*EE];      // gathered embeddings (sorted)
__device__ float g_embg[BB*TT*NG];      // emb @ W_ih[:, :512]^T + b_ih + b_hh (active rows only)
__device__ float g_hall[BB*TT*HH];      // h_new history for batched scores
__device__ float g_h[BB*HH];
__device__ float g_c[BB*HH];
__device__ float g_xch[BB*1024];        // [ctx | h_prev]
__device__ float g_Wg[NG*1024];         // [W_ih[:,512:1024] | W_hh]
__device__ float g_a2p[8][BB*AA];       // att2 split-K partials
__device__ float g_gp[4][BB*NG];        // gates split-K partials
__device__ int   g_sortidx[BB];
__device__ int   g_declen[BB];
__device__ int   g_act[BB*TT];
__device__ int   g_nact;

// ---------------- prep: stable argsort(-caplens) + active row list ----------------
__global__ void k_sort(const int* __restrict__ caplens, const int* __restrict__ caps,
                       float* __restrict__ out) {
    __shared__ int s_sort[BB];
    if (threadIdx.x == 0) {
        int cl[BB];
        for (int i = 0; i < BB; i++) cl[i] = caplens[i];
        int r = 0;
        for (int v = MAXCAP; v >= 0 && r < BB; v--)
            for (int i = 0; i < BB; i++)
                if (cl[i] == v) { g_sortidx[r] = i; s_sort[r] = i; r++; }
        int na = 0;
        for (int b = 0; b < BB; b++) {
            int dl = cl[g_sortidx[b]] - 1;
            g_declen[b] = dl;
            out[OFF_DECLEN + b] = (float)dl;
            out[OFF_SORT + b]   = (float)g_sortidx[b];
            for (int t = 0; t < dl; t++) g_act[na++] = b*TT + t;
        }
        g_nact = na;
    }
    __syncthreads();
    int b = threadIdx.x;
    int src = s_sort[b];
    for (int t = 0; t < MAXCAP; t++)
        out[OFF_CAPS + b*MAXCAP + t] = (float)caps[src*MAXCAP + t];
}

// ---------------- gathers / packs ----------------
__global__ void k_gather_feats(const float* __restrict__ imf) {
    int i = blockIdx.x*blockDim.x + threadIdx.x;
    const int per_b = PP*HH/4;
    if (i >= BB*per_b) return;
    int b = i / per_b, rest = i % per_b;
    ((float4*)g_feats)[i] = ((const float4*)imf)[(size_t)g_sortidx[b]*per_b + rest];
}

__global__ void k_gather_emb(const int* __restrict__ caps, const float* __restrict__ emb) {
    int i = blockIdx.x*blockDim.x + threadIdx.x;
    const int e4 = EE/4;
    if (i >= BB*TT*e4) return;
    int bt = i / e4;
    int b = bt / TT, t = bt % TT;
    int tok = caps[g_sortidx[b]*MAXCAP + t];
    ((float4*)g_embT)[i] = ((const float4*)emb)[(size_t)tok*e4 + (i % e4)];
}

__global__ void k_pack_wg(const float* __restrict__ W_ih, const float* __restrict__ W_hh) {
    int i = blockIdx.x*blockDim.x + threadIdx.x;
    if (i >= NG*256) return;               // 1024/4 = 256 float4 per row
    int j = i >> 8, k4 = i & 255;
    float4 v;
    if (k4 < 128) v = ((const float4*)W_ih)[j*256 + 128 + k4];
    else          v = ((const float4*)W_hh)[j*128 + (k4 - 128)];
    ((float4*)g_Wg)[i] = v;
}

__global__ void k_init_hc() {
    int i = blockIdx.x*blockDim.x + threadIdx.x;
    if (i < BB*HH) { g_h[i] = 0.f; g_c[i] = 0.f; }
}

__global__ void k_zero4(float* __restrict__ p, int n4) {
    int i = blockIdx.x*blockDim.x + threadIdx.x;
    if (i < n4) ((float4*)p)[i] = make_float4(0.f, 0.f, 0.f, 0.f);
}

// ---------------- generic big SGEMM: C[m,n] = A[row(m),:K] . B[n,:K] + bias ----------------
// BM=BN=128, BK=8, 256 threads, 8x8 micro-tile. rowmap!=null -> indexed rows, limit = g_nact.
__global__ __launch_bounds__(256)
void sgemm_nt(int M, int N, int K,
              const float* __restrict__ Ap, int lda,
              const float* __restrict__ Bp, int ldb,
              const float* __restrict__ bias1, const float* __restrict__ bias2,
              float* __restrict__ C, int ldc,
              const int* __restrict__ rowmap, int useNact)
{
    __shared__ float As[8][132];
    __shared__ float Bs[8][132];
    __shared__ int s_ml;
    int tid = threadIdx.x;
    if (tid == 0) s_ml = useNact ? g_nact : M;
    __syncthreads();
    int Ml = s_ml;
    int bm = blockIdx.x, bn = blockIdx.y;

    int arow = tid >> 1;
    int acol = (tid & 1) * 4;
    int gm = bm*128 + arow;
    long amap = -1;
    if (gm < Ml) amap = rowmap ? rowmap[gm] : gm;
    int gn = bn*128 + arow;
    bool bvalid = gn < N;
    int tx = tid & 15, ty = tid >> 4;

    float acc[8][8];
#pragma unroll
    for (int i = 0; i < 8; i++)
#pragma unroll
        for (int j = 0; j < 8; j++) acc[i][j] = 0.f;

    for (int k0 = 0; k0 < K; k0 += 8) {
        float4 av = make_float4(0,0,0,0), bv = make_float4(0,0,0,0);
        if (amap >= 0) av = *(const float4*)(Ap + amap*(long)lda + k0 + acol);
        if (bvalid)    bv = *(const float4*)(Bp + (long)gn*ldb + k0 + acol);
        __syncthreads();
        As[acol+0][arow] = av.x; As[acol+1][arow] = av.y;
        As[acol+2][arow] = av.z; As[acol+3][arow] = av.w;
        Bs[acol+0][arow] = bv.x; Bs[acol+1][arow] = bv.y;
        Bs[acol+2][arow] = bv.z; Bs[acol+3][arow] = bv.w;
        __syncthreads();
#pragma unroll
        for (int kk = 0; kk < 8; kk++) {
            float4 a0 = *(const float4*)(&As[kk][ty*8]);
            float4 a1 = *(const float4*)(&As[kk][ty*8+4]);
            float4 b0 = *(const float4*)(&Bs[kk][tx*8]);
            float4 b1 = *(const float4*)(&Bs[kk][tx*8+4]);
            float af[8] = {a0.x,a0.y,a0.z,a0.w,a1.x,a1.y,a1.z,a1.w};
            float bf[8] = {b0.x,b0.y,b0.z,b0.w,b1.x,b1.y,b1.z,b1.w};
#pragma unroll
            for (int i = 0; i < 8; i++)
#pragma unroll
                for (int j = 0; j < 8; j++)
                    acc[i][j] = fmaf(af[i], bf[j], acc[i][j]);
        }
    }
#pragma unroll
    for (int i = 0; i < 8; i++) {
        int m = bm*128 + ty*8 + i;
        if (m >= Ml) continue;
        long row = rowmap ? rowmap[m] : m;
#pragma unroll
        for (int j = 0; j < 8; j++) {
            int n = bn*128 + tx*8 + j;
            if (n >= N) continue;
            float v = acc[i][j];
            if (bias1) v += bias1[n];
            if (bias2) v += bias2[n];
            C[row*(long)ldc + n] = v;
        }
    }
}

// ---------------- small split-K GEMM, M=64 fixed: Cpart[ks][m*N+n] ----------------
__global__ __launch_bounds__(256)
void sgemm64_splitk(int N, int kchunk,
                    const float* __restrict__ Ap, int lda,
                    const float* __restrict__ Bp, int ldb,
                    float* __restrict__ Cpart)
{
    __shared__ float As[8][68];
    __shared__ float Bs[8][68];
    int tid = threadIdx.x;
    int bn = blockIdx.x, ks = blockIdx.y;
    int k0beg = ks * kchunk, k0end = k0beg + kchunk;

    int lrow = tid >> 2;
    int lcol = (tid & 3) * 2;
    int gn = bn*64 + lrow;
    int tx = tid & 15, ty = tid >> 4;

    float acc[4][4];
#pragma unroll
    for (int i = 0; i < 4; i++)
#pragma unroll
        for (int j = 0; j < 4; j++) acc[i][j] = 0.f;

    for (int k0 = k0beg; k0 < k0end; k0 += 8) {
        float2 av = *(const float2*)(Ap + lrow*lda + k0 + lcol);
        float2 bv = *(const float2*)(Bp + (long)gn*ldb + k0 + lcol);
        __syncthreads();
        As[lcol][lrow] = av.x; As[lcol+1][lrow] = av.y;
        Bs[lcol][lrow] = bv.x; Bs[lcol+1][lrow] = bv.y;
        __syncthreads();
#pragma unroll
        for (int kk = 0; kk < 8; kk++) {
            float4 a = *(const float4*)(&As[kk][ty*4]);
            float4 b = *(const float4*)(&Bs[kk][tx*4]);
            float af[4] = {a.x,a.y,a.z,a.w};
            float bf[4] = {b.x,b.y,b.z,b.w};
#pragma unroll
            for (int i = 0; i < 4; i++)
#pragma unroll
                for (int j = 0; j < 4; j++)
                    acc[i][j] = fmaf(af[i], bf[j], acc[i][j]);
        }
    }
    float* outp = Cpart + (long)ks*64*N + (long)bn*64;
#pragma unroll
    for (int i = 0; i < 4; i++)
#pragma unroll
        for (int j = 0; j < 4; j++)
            outp[(ty*4+i)*(long)N + tx*4 + j] = acc[i][j];
}

// ---------------- fused attention per batch row ----------------
__global__ __launch_bounds__(256)
void k_attn(int t, const float* __restrict__ b_dec, const float* __restrict__ W_full,
            const float* __restrict__ b_full, float* __restrict__ out)
{
    int b = blockIdx.x;
    int tid = threadIdx.x;
    __shared__ float s_att2[AA];
    __shared__ float s_wf[AA];
    __shared__ float s_e[PP];
    __shared__ float s_red[8];

    float* wout = out + OFF_WEIGHTS + (size_t)(b*TT + t) * PP;
    bool active = t < g_declen[b];
    if (!active) {
        for (int p = tid; p < PP; p += 256) wout[p] = 0.f;
        return;
    }

    for (int a = tid; a < AA; a += 256) {
        float v = b_dec[a];
#pragma unroll
        for (int s = 0; s < 8; s++) v += g_a2p[s][b*AA + a];
        s_att2[a] = v;
        s_wf[a] = W_full[a];
    }
    __syncthreads();

    int lane = tid & 31, w = tid >> 5;
    const float* ea = g_encatt + (size_t)b * PP * AA;
    for (int p = w; p < PP; p += 8) {
        const float* row = ea + (size_t)p * AA;
        float sum = 0.f;
        for (int a = lane; a < AA; a += 32)
            sum += fmaxf(row[a] + s_att2[a], 0.f) * s_wf[a];
#pragma unroll
        for (int o = 16; o; o >>= 1) sum += __shfl_xor_sync(0xffffffffu, sum, o);
        if (lane == 0) s_e[p] = sum + b_full[0];
    }
    __syncthreads();

    // softmax over PP=196
    float m = -1e30f;
    if (tid < PP) m = s_e[tid];
#pragma unroll
    for (int o = 16; o; o >>= 1) m = fmaxf(m, __shfl_xor_sync(0xffffffffu, m, o));
    if (lane == 0) s_red[w] = m;
    __syncthreads();
    float mx = s_red[0];
#pragma unroll
    for (int i = 1; i < 8; i++) mx = fmaxf(mx, s_red[i]);

    float ev = 0.f;
    if (tid < PP) ev = expf(s_e[tid] - mx);
    float sv = ev;
#pragma unroll
    for (int o = 16; o; o >>= 1) sv += __shfl_xor_sync(0xffffffffu, sv, o);
    __syncthreads();
    if (lane == 0) s_red[w] = sv;
    __syncthreads();
    float tot = 0.f;
#pragma unroll
    for (int i = 0; i < 8; i++) tot += s_red[i];
    float inv = 1.f / tot;
    if (tid < PP) {
        float al = ev * inv;
        s_e[tid] = al;
        wout[tid] = al;
    }
    __syncthreads();

    // ctx[h] = sum_p alpha[p] * feats[b][p][h];  also build x = [ctx | h_prev]
    const float* fb = g_feats + (size_t)b * PP * HH;
    for (int hh = tid; hh < HH; hh += 256) {
        float acc0 = 0.f;
        int p = 0;
#pragma unroll 4
        for (; p < PP; p++) acc0 = fmaf(s_e[p], fb[(size_t)p*HH + hh], acc0);
        g_xch[b*1024 + hh]       = acc0;
        g_xch[b*1024 + 512 + hh] = g_h[b*HH + hh];
    }
}

// ---------------- LSTM pointwise update ----------------
__global__ void k_lstm(int t) {
    int idx = blockIdx.x*blockDim.x + threadIdx.x;
    if (idx >= BB*HH) return;
    int b = idx >> 9, k = idx & 511;
    const float* eg = g_embg + (size_t)(b*TT + t) * NG;
    float gt[4];
#pragma unroll
    for (int q = 0; q < 4; q++) {
        int j = q*HH + k;
        float v = eg[j];
#pragma unroll
        for (int s = 0; s < 4; s++) v += g_gp[s][b*NG + j];
        gt[q] = v;
    }
    float ig = 1.f / (1.f + expf(-gt[0]));
    float fg = 1.f / (1.f + expf(-gt[1]));
    float gg = tanhf(gt[2]);
    float og = 1.f / (1.f + expf(-gt[3]));
    float c_new = fg * g_c[idx] + ig * gg;
    float h_new = og * tanhf(c_new);
    g_hall[(size_t)(b*TT + t)*HH + k] = h_new;
    if (t < g_declen[b]) { g_h[idx] = h_new; g_c[idx] = c_new; }
}

// ---------------- launch ----------------
extern "C" void kernel_launch(void* const* d_in, const int* in_sizes, int n_in,
                              void* d_out, int out_size) {
    const float* imf     = (const float*)d_in[0];
    const int*   caps    = (const int*)  d_in[1];
    const int*   caplens = (const int*)  d_in[2];
    const float* emb     = (const float*)d_in[3];
    const float* W_ih    = (const float*)d_in[4];
    const float* W_hh    = (const float*)d_in[5];
    const float* b_ih    = (const float*)d_in[6];
    const float* b_hh    = (const float*)d_in[7];
    const float* W_enc   = (const float*)d_in[8];
    const float* b_enc   = (const float*)d_in[9];
    const float* W_dec   = (const float*)d_in[10];
    const float* b_dec   = (const float*)d_in[11];
    const float* W_full  = (const float*)d_in[12];
    const float* b_full  = (const float*)d_in[13];
    const float* W_score = (const float*)d_in[14];
    const float* b_score = (const float*)d_in[15];
    float* out = (float*)d_out;

    float *p_feats, *p_encatt, *p_embT, *p_embg, *p_hall, *p_h, *p_xch, *p_Wg, *p_a2p, *p_gp;
    int *p_act;
    cudaGetSymbolAddress((void**)&p_feats,  g_feats);
    cudaGetSymbolAddress((void**)&p_encatt, g_encatt);
    cudaGetSymbolAddress((void**)&p_embT,   g_embT);
    cudaGetSymbolAddress((void**)&p_embg,   g_embg);
    cudaGetSymbolAddress((void**)&p_hall,   g_hall);
    cudaGetSymbolAddress((void**)&p_h,      g_h);
    cudaGetSymbolAddress((void**)&p_xch,    g_xch);
    cudaGetSymbolAddress((void**)&p_Wg,     g_Wg);
    cudaGetSymbolAddress((void**)&p_a2p,    g_a2p);
    cudaGetSymbolAddress((void**)&p_gp,     g_gp);
    cudaGetSymbolAddress((void**)&p_act,    g_act);

    // prep
    k_sort<<<1, BB>>>(caplens, caps, out);
    k_gather_feats<<<(BB*PP*HH/4 + 255)/256, 256>>>(imf);
    k_gather_emb<<<(BB*TT*EE/4 + 255)/256, 256>>>(caps, emb);
    k_pack_wg<<<(NG*256 + 255)/256, 256>>>(W_ih, W_hh);
    k_init_hc<<<(BB*HH + 255)/256, 256>>>();
    k_zero4<<<(N_SCORES/4 + 255)/256, 256>>>(out, N_SCORES/4);

    // enc_att = feats @ W_enc^T + b_enc   (M=12544, N=512, K=512)
    {
        dim3 g((BB*PP + 127)/128, (AA + 127)/128);
        sgemm_nt<<<g, 256>>>(BB*PP, AA, HH, p_feats, HH, W_enc, HH,
                             b_enc, nullptr, p_encatt, AA, nullptr, 0);
    }
    // G_emb = emb @ W_ih[:, :512]^T + b_ih + b_hh  (active rows only)
    {
        dim3 g((BB*TT + 127)/128, (NG + 127)/128);
        sgemm_nt<<<g, 256>>>(BB*TT, NG, EE, p_embT, EE, W_ih, 1024,
                             b_ih, b_hh, p_embg, NG, p_act, 1);
    }

    // recurrence
    for (int t = 0; t < TT; t++) {
        sgemm64_splitk<<<dim3(AA/64, 8), 256>>>(AA, HH/8, p_h, HH, W_dec, HH, p_a2p);
        k_attn<<<BB, 256>>>(t, b_dec, W_full, b_full, out);
        sgemm64_splitk<<<dim3(NG/64, 4), 256>>>(NG, 1024/4, p_xch, 1024, p_Wg, 1024, p_gp);
        k_lstm<<<(BB*HH + 255)/256, 256>>>(t);
    }

    // scores = h_all @ W_score^T + b_score  (active rows, direct masked write)
    {
        dim3 g((BB*TT + 127)/128, (VV + 127)/128);
        sgemm_nt<<<g, 256>>>(BB*TT, VV, HH, p_hall, HH, W_score, HH,
                             b_score, nullptr, out, VV, p_act, 1);
    }
}

// round 3
// speedup vs baseline: 1.1881x; 1.1881x over previous
#include <cuda_runtime.h>
#include <cuda_bf16.h>
#include <cstdint>
#include <math.h>

#define BB 64
#define PP 196
#define HH 512
#define EE 512
#define AA 512
#define VV 10000
#define MAXCAP 50
#define TT 49
#define NG 2048   // 4*H

// output layout (float32): scores (B,T,V), caps_s (B,50), decode_lengths (B,), weights (B,T,P), sort_ind (B,)
#define N_SCORES   (BB*TT*VV)
#define OFF_CAPS   (N_SCORES)
#define OFF_DECLEN (OFF_CAPS + BB*MAXCAP)
#define OFF_WEIGHTS (OFF_DECLEN + BB)
#define OFF_SORT   (OFF_WEIGHTS + BB*TT*PP)

// ======================= scratch =======================
__device__ float g_feats[BB*PP*HH];
__device__ float g_encatt[BB*PP*AA];
__device__ float g_embT[BB*TT*EE];
__device__ float g_embg[BB*TT*NG];
__device__ float g_hall[BB*TT*HH];
__device__ float g_h[BB*HH];
__device__ float g_c[BB*HH];
__device__ float g_xch[BB*1024];
__device__ float g_Wg[NG*1024];
__device__ float g_a2p[8][BB*AA];
__device__ float g_gp[4][BB*NG];
__device__ int   g_sortidx[BB];
__device__ int   g_declen[BB];
__device__ int   g_act[BB*TT];
__device__ int   g_nact;

// bf16 hi/lo packed [rows][1024]: cols 0-511 hi, 512-1023 lo
__device__ __nv_bfloat16 g_feats2[BB*PP*1024];
__device__ __nv_bfloat16 g_embT2[BB*TT*1024];
__device__ __nv_bfloat16 g_hall2[BB*TT*1024];
__device__ __nv_bfloat16 g_Wenc2[AA*1024];
__device__ __nv_bfloat16 g_Wih2[NG*1024];
__device__ __nv_bfloat16 g_Wsc2[VV*1024];

// ======================= prep kernels =======================
__global__ void k_sort(const int* __restrict__ caplens, const int* __restrict__ caps,
                       float* __restrict__ out) {
    __shared__ int s_sort[BB];
    if (threadIdx.x == 0) {
        int cl[BB];
        for (int i = 0; i < BB; i++) cl[i] = caplens[i];
        int r = 0;
        for (int v = MAXCAP; v >= 0 && r < BB; v--)
            for (int i = 0; i < BB; i++)
                if (cl[i] == v) { g_sortidx[r] = i; s_sort[r] = i; r++; }
        int na = 0;
        for (int b = 0; b < BB; b++) {
            int dl = cl[g_sortidx[b]] - 1;
            g_declen[b] = dl;
            out[OFF_DECLEN + b] = (float)dl;
            out[OFF_SORT + b]   = (float)g_sortidx[b];
            for (int t = 0; t < dl; t++) g_act[na++] = b*TT + t;
        }
        g_nact = na;
    }
    __syncthreads();
    int b = threadIdx.x;
    int src = s_sort[b];
    for (int t = 0; t < MAXCAP; t++)
        out[OFF_CAPS + b*MAXCAP + t] = (float)caps[src*MAXCAP + t];
}

__global__ void k_gather_feats(const float* __restrict__ imf) {
    int i = blockIdx.x*blockDim.x + threadIdx.x;
    const int per_b = PP*HH/4;
    if (i >= BB*per_b) return;
    int b = i / per_b, rest = i % per_b;
    ((float4*)g_feats)[i] = ((const float4*)imf)[(size_t)g_sortidx[b]*per_b + rest];
}

__global__ void k_gather_emb(const int* __restrict__ caps, const float* __restrict__ emb) {
    int i = blockIdx.x*blockDim.x + threadIdx.x;
    const int e4 = EE/4;
    if (i >= BB*TT*e4) return;
    int bt = i / e4;
    int b = bt / TT, t = bt % TT;
    int tok = caps[g_sortidx[b]*MAXCAP + t];
    ((float4*)g_embT)[i] = ((const float4*)emb)[(size_t)tok*e4 + (i % e4)];
}

__global__ void k_pack_wg(const float* __restrict__ W_ih, const float* __restrict__ W_hh) {
    int i = blockIdx.x*blockDim.x + threadIdx.x;
    if (i >= NG*256) return;
    int j = i >> 8, k4 = i & 255;
    float4 v;
    if (k4 < 128) v = ((const float4*)W_ih)[j*256 + 128 + k4];
    else          v = ((const float4*)W_hh)[j*128 + (k4 - 128)];
    ((float4*)g_Wg)[i] = v;
}

__global__ void k_init_hc() {
    int i = blockIdx.x*blockDim.x + threadIdx.x;
    if (i < BB*HH) { g_h[i] = 0.f; g_c[i] = 0.f; }
}

__global__ void k_zero4(float* __restrict__ p, int n4) {
    int i = blockIdx.x*blockDim.x + threadIdx.x;
    if (i < n4) ((float4*)p)[i] = make_float4(0.f, 0.f, 0.f, 0.f);
}

// fp32 -> bf16 hi/lo split
__global__ void k_cvt_hilo(const float* __restrict__ src, int srcld,
                           __nv_bfloat16* __restrict__ dst, int rows) {
    int i = blockIdx.x*blockDim.x + threadIdx.x;
    if (i >= rows*512) return;
    int r = i >> 9, c = i & 511;
    float v = src[(size_t)r*srcld + c];
    __nv_bfloat16 hi = __float2bfloat16(v);
    float lo = v - __bfloat162float(hi);
    dst[(size_t)r*1024 + c]       = hi;
    dst[(size_t)r*1024 + 512 + c] = __float2bfloat16(lo);
}

// ======================= mma.sync bf16x3 GEMM =======================
// C[row(m), n] = sum over 3 terms (Ah*Bh, Ah*Bl, Al*Bh) of A2[row, ka+k] . B2[n, kb+k]
// A2, B2: [*, 1024] bf16 (hi | lo). CTA tile 128x128, BK=32, 8 warps (2Mx4N), warp 64x32.
__device__ __forceinline__ uint32_t ldsw(const __nv_bfloat16* s, int row, int kpair) {
    int byte = row*64 + ((((kpair >> 2) ^ ((row >> 1) & 3))) << 4) + ((kpair & 3) << 2);
    return *(const uint32_t*)((const char*)s + byte);
}
__device__ __forceinline__ void mma16816(float* d, const uint32_t* a, const uint32_t* b) {
    asm volatile("mma.sync.aligned.m16n8k16.row.col.f32.bf16.bf16.f32 "
        "{%0,%1,%2,%3}, {%4,%5,%6,%7}, {%8,%9}, {%0,%1,%2,%3};"
        : "+f"(d[0]), "+f"(d[1]), "+f"(d[2]), "+f"(d[3])
        : "r"(a[0]), "r"(a[1]), "r"(a[2]), "r"(a[3]), "r"(b[0]), "r"(b[1]));
}

__global__ __launch_bounds__(256)
void hgemm(const __nv_bfloat16* __restrict__ A2,
           const __nv_bfloat16* __restrict__ B2,
           int M, int N, int ldc,
           const float* __restrict__ bias1, const float* __restrict__ bias2,
           float* __restrict__ C,
           const int* __restrict__ rowmap, int use_nact)
{
    __shared__ __align__(16) __nv_bfloat16 As[128*32];
    __shared__ __align__(16) __nv_bfloat16 Bs[128*32];
    int tid = threadIdx.x;
    int Ml = use_nact ? g_nact : M;
    int bm = blockIdx.x, bn = blockIdx.y;
    if (bm*128 >= Ml) return;

    // ---- global load setup: each thread loads 2x16B for A and B ----
    int lrow = tid >> 1;
    int lc0 = (tid & 1) * 2;                 // chunks lc0, lc0+1 (16B units of 8 bf16)
    int gm = bm*128 + lrow;
    const uint4* arow = nullptr;
    if (gm < Ml) { int r = rowmap ? rowmap[gm] : gm; arow = (const uint4*)(A2 + (size_t)r*1024); }
    int gn = bn*128 + lrow;
    const uint4* brow = (gn < N) ? (const uint4*)(B2 + (size_t)gn*1024) : nullptr;

    int swz = (lrow >> 1) & 3;
    uint4* asw0 = (uint4*)(As + lrow*32) + (lc0 ^ swz);
    uint4* asw1 = (uint4*)(As + lrow*32) + ((lc0+1) ^ swz);
    uint4* bsw0 = (uint4*)(Bs + lrow*32) + (lc0 ^ swz);
    uint4* bsw1 = (uint4*)(Bs + lrow*32) + ((lc0+1) ^ swz);

    int lane = tid & 31, wid = tid >> 5;
    int wm = (wid >> 2) * 64;    // warp M offset in tile
    int wn = (wid & 3) * 32;     // warp N offset in tile
    int gq = lane >> 2, tg = lane & 3;

    float acc[4][4][4];
#pragma unroll
    for (int mt = 0; mt < 4; mt++)
#pragma unroll
        for (int nt = 0; nt < 4; nt++)
#pragma unroll
            for (int r = 0; r < 4; r++) acc[mt][nt][r] = 0.f;

    const uint4 z = make_uint4(0,0,0,0);
    uint4 pa0, pa1, pb0, pb1;
    // ka/kb uint4 offsets per term: (Ah,Bh) (Ah,Bl) (Al,Bh); lo half starts at col 512 = u4 64
    const int kau4[3] = {0, 0, 64};
    const int kbu4[3] = {0, 64, 0};
    {
        pa0 = arow ? arow[lc0]   : z;
        pa1 = arow ? arow[lc0+1] : z;
        pb0 = brow ? brow[lc0]   : z;
        pb1 = brow ? brow[lc0+1] : z;
    }

    for (int ci = 0; ci < 48; ci++) {
        __syncthreads();
        *asw0 = pa0; *asw1 = pa1; *bsw0 = pb0; *bsw1 = pb1;
        __syncthreads();
        if (ci + 1 < 48) {
            int term = (ci+1) >> 4, kc = (ci+1) & 15;
            int ab = kau4[term] + kc*4, bb = kbu4[term] + kc*4;
            pa0 = arow ? arow[ab + lc0]   : z;
            pa1 = arow ? arow[ab + lc0+1] : z;
            pb0 = brow ? brow[bb + lc0]   : z;
            pb1 = brow ? brow[bb + lc0+1] : z;
        }
#pragma unroll
        for (int kk = 0; kk < 2; kk++) {
            int kp0 = kk*8 + tg;
            int kp1 = kp0 + 4;
            uint32_t afr[4][4];
#pragma unroll
            for (int mt = 0; mt < 4; mt++) {
                int r0 = wm + mt*16 + gq;
                afr[mt][0] = ldsw(As, r0,     kp0);
                afr[mt][1] = ldsw(As, r0 + 8, kp0);
                afr[mt][2] = ldsw(As, r0,     kp1);
                afr[mt][3] = ldsw(As, r0 + 8, kp1);
            }
            uint32_t bfr[4][2];
#pragma unroll
            for (int nt = 0; nt < 4; nt++) {
                int rn = wn + nt*8 + gq;
                bfr[nt][0] = ldsw(Bs, rn, kp0);
                bfr[nt][1] = ldsw(Bs, rn, kp1);
            }
#pragma unroll
            for (int mt = 0; mt < 4; mt++)
#pragma unroll
                for (int nt = 0; nt < 4; nt++)
                    mma16816(acc[mt][nt], afr[mt], bfr[nt]);
        }
    }

    // ---- epilogue ----
#pragma unroll
    for (int mt = 0; mt < 4; mt++) {
        int m0 = bm*128 + wm + mt*16 + gq;
        int m1 = m0 + 8;
        size_t row0 = 0, row1 = 0;
        bool v0 = m0 < Ml, v1 = m1 < Ml;
        if (v0) row0 = (size_t)(rowmap ? rowmap[m0] : m0);
        if (v1) row1 = (size_t)(rowmap ? rowmap[m1] : m1);
#pragma unroll
        for (int nt = 0; nt < 4; nt++) {
            int col = bn*128 + wn + nt*8 + tg*2;
            if (col >= N) continue;
            float bx = bias1[col], by = bias1[col+1];
            if (bias2) { bx += bias2[col]; by += bias2[col+1]; }
            if (v0) {
                float2 o = make_float2(acc[mt][nt][0] + bx, acc[mt][nt][1] + by);
                *(float2*)(C + row0*(size_t)ldc + col) = o;
            }
            if (v1) {
                float2 o = make_float2(acc[mt][nt][2] + bx, acc[mt][nt][3] + by);
                *(float2*)(C + row1*(size_t)ldc + col) = o;
            }
        }
    }
}

// ======================= recurrence kernels (fp32) =======================
__global__ __launch_bounds__(256)
void sgemm64_splitk(int N, int kchunk,
                    const float* __restrict__ Ap, int lda,
                    const float* __restrict__ Bp, int ldb,
                    float* __restrict__ Cpart)
{
    __shared__ float As[8][68];
    __shared__ float Bs[8][68];
    int tid = threadIdx.x;
    int bn = blockIdx.x, ks = blockIdx.y;
    int k0beg = ks * kchunk, k0end = k0beg + kchunk;

    int lrow = tid >> 2;
    int lcol = (tid & 3) * 2;
    int gn = bn*64 + lrow;
    int tx = tid & 15, ty = tid >> 4;

    float acc[4][4];
#pragma unroll
    for (int i = 0; i < 4; i++)
#pragma unroll
        for (int j = 0; j < 4; j++) acc[i][j] = 0.f;

    for (int k0 = k0beg; k0 < k0end; k0 += 8) {
        float2 av = *(const float2*)(Ap + lrow*lda + k0 + lcol);
        float2 bv = *(const float2*)(Bp + (long)gn*ldb + k0 + lcol);
        __syncthreads();
        As[lcol][lrow] = av.x; As[lcol+1][lrow] = av.y;
        Bs[lcol][lrow] = bv.x; Bs[lcol+1][lrow] = bv.y;
        __syncthreads();
#pragma unroll
        for (int kk = 0; kk < 8; kk++) {
            float4 a = *(const float4*)(&As[kk][ty*4]);
            float4 b = *(const float4*)(&Bs[kk][tx*4]);
            float af[4] = {a.x,a.y,a.z,a.w};
            float bf[4] = {b.x,b.y,b.z,b.w};
#pragma unroll
            for (int i = 0; i < 4; i++)
#pragma unroll
                for (int j = 0; j < 4; j++)
                    acc[i][j] = fmaf(af[i], bf[j], acc[i][j]);
        }
    }
    float* outp = Cpart + (long)ks*64*N + (long)bn*64;
#pragma unroll
    for (int i = 0; i < 4; i++)
#pragma unroll
        for (int j = 0; j < 4; j++)
            outp[(ty*4+i)*(long)N + tx*4 + j] = acc[i][j];
}

__global__ __launch_bounds__(256)
void k_attn(int t, const float* __restrict__ b_dec, const float* __restrict__ W_full,
            const float* __restrict__ b_full, float* __restrict__ out)
{
    int b = blockIdx.x;
    int tid = threadIdx.x;
    __shared__ float s_att2[AA];
    __shared__ float s_wf[AA];
    __shared__ float s_e[PP];
    __shared__ float s_red[8];

    float* wout = out + OFF_WEIGHTS + (size_t)(b*TT + t) * PP;
    bool active = t < g_declen[b];
    if (!active) {
        for (int p = tid; p < PP; p += 256) wout[p] = 0.f;
        return;
    }

    for (int a = tid; a < AA; a += 256) {
        float v = b_dec[a];
#pragma unroll
        for (int s = 0; s < 8; s++) v += g_a2p[s][b*AA + a];
        s_att2[a] = v;
        s_wf[a] = W_full[a];
    }
    __syncthreads();

    int lane = tid & 31, w = tid >> 5;
    const float* ea = g_encatt + (size_t)b * PP * AA;
    for (int p = w; p < PP; p += 8) {
        const float* row = ea + (size_t)p * AA;
        float sum = 0.f;
        for (int a = lane; a < AA; a += 32)
            sum += fmaxf(row[a] + s_att2[a], 0.f) * s_wf[a];
#pragma unroll
        for (int o = 16; o; o >>= 1) sum += __shfl_xor_sync(0xffffffffu, sum, o);
        if (lane == 0) s_e[p] = sum + b_full[0];
    }
    __syncthreads();

    float m = -1e30f;
    if (tid < PP) m = s_e[tid];
#pragma unroll
    for (int o = 16; o; o >>= 1) m = fmaxf(m, __shfl_xor_sync(0xffffffffu, m, o));
    if (lane == 0) s_red[w] = m;
    __syncthreads();
    float mx = s_red[0];
#pragma unroll
    for (int i = 1; i < 8; i++) mx = fmaxf(mx, s_red[i]);

    float ev = 0.f;
    if (tid < PP) ev = expf(s_e[tid] - mx);
    float sv = ev;
#pragma unroll
    for (int o = 16; o; o >>= 1) sv += __shfl_xor_sync(0xffffffffu, sv, o);
    __syncthreads();
    if (lane == 0) s_red[w] = sv;
    __syncthreads();
    float tot = 0.f;
#pragma unroll
    for (int i = 0; i < 8; i++) tot += s_red[i];
    float inv = 1.f / tot;
    if (tid < PP) {
        float al = ev * inv;
        s_e[tid] = al;
        wout[tid] = al;
    }
    __syncthreads();

    const float* fb = g_feats + (size_t)b * PP * HH;
    for (int hh = tid; hh < HH; hh += 256) {
        float acc0 = 0.f;
#pragma unroll 4
        for (int p = 0; p < PP; p++) acc0 = fmaf(s_e[p], fb[(size_t)p*HH + hh], acc0);
        g_xch[b*1024 + hh]       = acc0;
        g_xch[b*1024 + 512 + hh] = g_h[b*HH + hh];
    }
}

__global__ void k_lstm(int t) {
    int idx = blockIdx.x*blockDim.x + threadIdx.x;
    if (idx >= BB*HH) return;
    int b = idx >> 9, k = idx & 511;
    const float* eg = g_embg + (size_t)(b*TT + t) * NG;
    float gt[4];
#pragma unroll
    for (int q = 0; q < 4; q++) {
        int j = q*HH + k;
        float v = eg[j];
#pragma unroll
        for (int s = 0; s < 4; s++) v += g_gp[s][b*NG + j];
        gt[q] = v;
    }
    float ig = 1.f / (1.f + expf(-gt[0]));
    float fg = 1.f / (1.f + expf(-gt[1]));
    float gg = tanhf(gt[2]);
    float og = 1.f / (1.f + expf(-gt[3]));
    float c_new = fg * g_c[idx] + ig * gg;
    float h_new = og * tanhf(c_new);
    g_hall[(size_t)(b*TT + t)*HH + k] = h_new;
    if (t < g_declen[b]) { g_h[idx] = h_new; g_c[idx] = c_new; }
}

// ======================= launch =======================
extern "C" void kernel_launch(void* const* d_in, const int* in_sizes, int n_in,
                              void* d_out, int out_size) {
    const float* imf     = (const float*)d_in[0];
    const int*   caps    = (const int*)  d_in[1];
    const int*   caplens = (const int*)  d_in[2];
    const float* emb     = (const float*)d_in[3];
    const float* W_ih    = (const float*)d_in[4];
    const float* W_hh    = (const float*)d_in[5];
    const float* b_ih    = (const float*)d_in[6];
    const float* b_hh    = (const float*)d_in[7];
    const float* W_enc   = (const float*)d_in[8];
    const float* b_enc   = (const float*)d_in[9];
    const float* W_dec   = (const float*)d_in[10];
    const float* b_dec   = (const float*)d_in[11];
    const float* W_full  = (const float*)d_in[12];
    const float* b_full  = (const float*)d_in[13];
    const float* W_score = (const float*)d_in[14];
    const float* b_score = (const float*)d_in[15];
    float* out = (float*)d_out;

    float *p_feats, *p_encatt, *p_embT, *p_embg, *p_hall, *p_h, *p_xch, *p_Wg, *p_a2p, *p_gp;
    int *p_act;
    __nv_bfloat16 *p_feats2, *p_embT2, *p_hall2, *p_Wenc2, *p_Wih2, *p_Wsc2;
    cudaGetSymbolAddress((void**)&p_feats,  g_feats);
    cudaGetSymbolAddress((void**)&p_encatt, g_encatt);
    cudaGetSymbolAddress((void**)&p_embT,   g_embT);
    cudaGetSymbolAddress((void**)&p_embg,   g_embg);
    cudaGetSymbolAddress((void**)&p_hall,   g_hall);
    cudaGetSymbolAddress((void**)&p_h,      g_h);
    cudaGetSymbolAddress((void**)&p_xch,    g_xch);
    cudaGetSymbolAddress((void**)&p_Wg,     g_Wg);
    cudaGetSymbolAddress((void**)&p_a2p,    g_a2p);
    cudaGetSymbolAddress((void**)&p_gp,     g_gp);
    cudaGetSymbolAddress((void**)&p_act,    g_act);
    cudaGetSymbolAddress((void**)&p_feats2, g_feats2);
    cudaGetSymbolAddress((void**)&p_embT2,  g_embT2);
    cudaGetSymbolAddress((void**)&p_hall2,  g_hall2);
    cudaGetSymbolAddress((void**)&p_Wenc2,  g_Wenc2);
    cudaGetSymbolAddress((void**)&p_Wih2,   g_Wih2);
    cudaGetSymbolAddress((void**)&p_Wsc2,   g_Wsc2);

    // prep
    k_sort<<<1, BB>>>(caplens, caps, out);
    k_gather_feats<<<(BB*PP*HH/4 + 255)/256, 256>>>(imf);
    k_gather_emb<<<(BB*TT*EE/4 + 255)/256, 256>>>(caps, emb);
    k_pack_wg<<<(NG*256 + 255)/256, 256>>>(W_ih, W_hh);
    k_init_hc<<<(BB*HH + 255)/256, 256>>>();
    k_zero4<<<(N_SCORES/4 + 255)/256, 256>>>(out, N_SCORES/4);

    // bf16 hi/lo conversions
    k_cvt_hilo<<<(BB*PP*512 + 255)/256, 256>>>(p_feats, HH, p_feats2, BB*PP);
    k_cvt_hilo<<<(BB*TT*512 + 255)/256, 256>>>(p_embT, EE, p_embT2, BB*TT);
    k_cvt_hilo<<<(AA*512 + 255)/256, 256>>>(W_enc, HH, p_Wenc2, AA);
    k_cvt_hilo<<<(NG*512 + 255)/256, 256>>>(W_ih, 1024, p_Wih2, NG);
    k_cvt_hilo<<<(VV*512 + 255)/256, 256>>>(W_score, HH, p_Wsc2, VV);

    // enc_att = feats @ W_enc^T + b_enc   (M=12544, N=512)
    hgemm<<<dim3((BB*PP + 127)/128, (AA + 127)/128), 256>>>(
        p_feats2, p_Wenc2, BB*PP, AA, AA, b_enc, nullptr, p_encatt, nullptr, 0);
    // G_emb = emb @ W_ih[:, :512]^T + b_ih + b_hh  (active rows)
    hgemm<<<dim3((BB*TT + 127)/128, (NG + 127)/128), 256>>>(
        p_embT2, p_Wih2, BB*TT, NG, NG, b_ih, b_hh, p_embg, p_act, 1);

    // recurrence
    for (int t = 0; t < TT; t++) {
        sgemm64_splitk<<<dim3(AA/64, 8), 256>>>(AA, HH/8, p_h, HH, W_dec, HH, p_a2p);
        k_attn<<<BB, 256>>>(t, b_dec, W_full, b_full, out);
        sgemm64_splitk<<<dim3(NG/64, 4), 256>>>(NG, 1024/4, p_xch, 1024, p_Wg, 1024, p_gp);
        k_lstm<<<(BB*HH + 255)/256, 256>>>(t);
    }

    // scores = h_all @ W_score^T + b_score (active rows)
    k_cvt_hilo<<<(BB*TT*512 + 255)/256, 256>>>(p_hall, HH, p_hall2, BB*TT);
    hgemm<<<dim3((BB*TT + 127)/128, (VV + 127)/128), 256>>>(
        p_hall2, p_Wsc2, BB*TT, VV, VV, b_score, nullptr, out, p_act, 1);
}

// round 4
// speedup vs baseline: 1.4434x; 1.2149x over previous
#include <cuda_runtime.h>
#include <cuda_bf16.h>
#include <cstdint>
#include <math.h>

#define BB 64
#define PP 196
#define HH 512
#define EE 512
#define AA 512
#define VV 10000
#define MAXCAP 50
#define TT 49
#define NG 2048   // 4*H

// output layout (float32): scores (B,T,V), caps_s (B,50), decode_lengths (B,), weights (B,T,P), sort_ind (B,)
#define N_SCORES   (BB*TT*VV)
#define OFF_CAPS   (N_SCORES)
#define OFF_DECLEN (OFF_CAPS + BB*MAXCAP)
#define OFF_WEIGHTS (OFF_DECLEN + BB)
#define OFF_SORT   (OFF_WEIGHTS + BB*TT*PP)

#define NCTA 128
#define NTHR 256

// ======================= scratch =======================
__device__ float g_feats[BB*PP*HH];
__device__ float g_encatt[BB*PP*AA];
__device__ float g_embT[BB*TT*EE];
__device__ float g_embg[BB*TT*NG];
__device__ float g_hall[BB*TT*HH];
__device__ float g_h[BB*HH];
__device__ float g_c[BB*HH];
__device__ float g_att2[BB*AA];
__device__ float g_ctx[BB*HH];
__device__ int   g_sortidx[BB];
__device__ int   g_declen[BB];
__device__ int   g_act[BB*TT];
__device__ int   g_nact;
__device__ int   g_bar;

// bf16 hi/lo packed [rows][1024]: cols 0-511 hi, 512-1023 lo
__device__ __nv_bfloat16 g_feats2[BB*PP*1024];
__device__ __nv_bfloat16 g_embT2[BB*TT*1024];
__device__ __nv_bfloat16 g_hall2[BB*TT*1024];
__device__ __nv_bfloat16 g_Wenc2[AA*1024];
__device__ __nv_bfloat16 g_Wih2[NG*1024];
__device__ __nv_bfloat16 g_Wsc2[VV*1024];

// ======================= prep kernels =======================
__global__ void k_sort(const int* __restrict__ caplens, const int* __restrict__ caps,
                       float* __restrict__ out) {
    __shared__ int s_sort[BB];
    if (threadIdx.x == 0) {
        int cl[BB];
        for (int i = 0; i < BB; i++) cl[i] = caplens[i];
        int r = 0;
        for (int v = MAXCAP; v >= 0 && r < BB; v--)
            for (int i = 0; i < BB; i++)
                if (cl[i] == v) { g_sortidx[r] = i; s_sort[r] = i; r++; }
        int na = 0;
        for (int b = 0; b < BB; b++) {
            int dl = cl[g_sortidx[b]] - 1;
            g_declen[b] = dl;
            out[OFF_DECLEN + b] = (float)dl;
            out[OFF_SORT + b]   = (float)g_sortidx[b];
            for (int t = 0; t < dl; t++) g_act[na++] = b*TT + t;
        }
        g_nact = na;
    }
    __syncthreads();
    int b = threadIdx.x;
    int src = s_sort[b];
    for (int t = 0; t < MAXCAP; t++)
        out[OFF_CAPS + b*MAXCAP + t] = (float)caps[src*MAXCAP + t];
}

__global__ void k_gather_feats(const float* __restrict__ imf) {
    int i = blockIdx.x*blockDim.x + threadIdx.x;
    const int per_b = PP*HH/4;
    if (i >= BB*per_b) return;
    int b = i / per_b, rest = i % per_b;
    ((float4*)g_feats)[i] = ((const float4*)imf)[(size_t)g_sortidx[b]*per_b + rest];
}

__global__ void k_gather_emb(const int* __restrict__ caps, const float* __restrict__ emb) {
    int i = blockIdx.x*blockDim.x + threadIdx.x;
    const int e4 = EE/4;
    if (i >= BB*TT*e4) return;
    int bt = i / e4;
    int b = bt / TT, t = bt % TT;
    int tok = caps[g_sortidx[b]*MAXCAP + t];
    ((float4*)g_embT)[i] = ((const float4*)emb)[(size_t)tok*e4 + (i % e4)];
}

__global__ void k_init() {
    int i = blockIdx.x*blockDim.x + threadIdx.x;
    if (i < BB*HH) { g_h[i] = 0.f; g_c[i] = 0.f; }
    if (i == 0) g_bar = 0;
}

__global__ void k_zero4(float* __restrict__ p, int n4) {
    int i = blockIdx.x*blockDim.x + threadIdx.x;
    if (i < n4) ((float4*)p)[i] = make_float4(0.f, 0.f, 0.f, 0.f);
}

// fp32 -> bf16 hi/lo split
__global__ void k_cvt_hilo(const float* __restrict__ src, int srcld,
                           __nv_bfloat16* __restrict__ dst, int rows) {
    int i = blockIdx.x*blockDim.x + threadIdx.x;
    if (i >= rows*512) return;
    int r = i >> 9, c = i & 511;
    float v = src[(size_t)r*srcld + c];
    __nv_bfloat16 hi = __float2bfloat16(v);
    float lo = v - __bfloat162float(hi);
    dst[(size_t)r*1024 + c]       = hi;
    dst[(size_t)r*1024 + 512 + c] = __float2bfloat16(lo);
}

// ======================= mma.sync bf16x3 GEMM (unchanged, verified) =======================
__device__ __forceinline__ uint32_t ldsw(const __nv_bfloat16* s, int row, int kpair) {
    int byte = row*64 + ((((kpair >> 2) ^ ((row >> 1) & 3))) << 4) + ((kpair & 3) << 2);
    return *(const uint32_t*)((const char*)s + byte);
}
__device__ __forceinline__ void mma16816(float* d, const uint32_t* a, const uint32_t* b) {
    asm volatile("mma.sync.aligned.m16n8k16.row.col.f32.bf16.bf16.f32 "
        "{%0,%1,%2,%3}, {%4,%5,%6,%7}, {%8,%9}, {%0,%1,%2,%3};"
        : "+f"(d[0]), "+f"(d[1]), "+f"(d[2]), "+f"(d[3])
        : "r"(a[0]), "r"(a[1]), "r"(a[2]), "r"(a[3]), "r"(b[0]), "r"(b[1]));
}

__global__ __launch_bounds__(256)
void hgemm(const __nv_bfloat16* __restrict__ A2,
           const __nv_bfloat16* __restrict__ B2,
           int M, int N, int ldc,
           const float* __restrict__ bias1, const float* __restrict__ bias2,
           float* __restrict__ C,
           const int* __restrict__ rowmap, int use_nact)
{
    __shared__ __align__(16) __nv_bfloat16 As[128*32];
    __shared__ __align__(16) __nv_bfloat16 Bs[128*32];
    int tid = threadIdx.x;
    int Ml = use_nact ? g_nact : M;
    int bm = blockIdx.x, bn = blockIdx.y;
    if (bm*128 >= Ml) return;

    int lrow = tid >> 1;
    int lc0 = (tid & 1) * 2;
    int gm = bm*128 + lrow;
    const uint4* arow = nullptr;
    if (gm < Ml) { int r = rowmap ? rowmap[gm] : gm; arow = (const uint4*)(A2 + (size_t)r*1024); }
    int gn = bn*128 + lrow;
    const uint4* brow = (gn < N) ? (const uint4*)(B2 + (size_t)gn*1024) : nullptr;

    int swz = (lrow >> 1) & 3;
    uint4* asw0 = (uint4*)(As + lrow*32) + (lc0 ^ swz);
    uint4* asw1 = (uint4*)(As + lrow*32) + ((lc0+1) ^ swz);
    uint4* bsw0 = (uint4*)(Bs + lrow*32) + (lc0 ^ swz);
    uint4* bsw1 = (uint4*)(Bs + lrow*32) + ((lc0+1) ^ swz);

    int lane = tid & 31, wid = tid >> 5;
    int wm = (wid >> 2) * 64;
    int wn = (wid & 3) * 32;
    int gq = lane >> 2, tg = lane & 3;

    float acc[4][4][4];
#pragma unroll
    for (int mt = 0; mt < 4; mt++)
#pragma unroll
        for (int nt = 0; nt < 4; nt++)
#pragma unroll
            for (int r = 0; r < 4; r++) acc[mt][nt][r] = 0.f;

    const uint4 z = make_uint4(0,0,0,0);
    uint4 pa0, pa1, pb0, pb1;
    const int kau4[3] = {0, 0, 64};
    const int kbu4[3] = {0, 64, 0};
    {
        pa0 = arow ? arow[lc0]   : z;
        pa1 = arow ? arow[lc0+1] : z;
        pb0 = brow ? brow[lc0]   : z;
        pb1 = brow ? brow[lc0+1] : z;
    }

    for (int ci = 0; ci < 48; ci++) {
        __syncthreads();
        *asw0 = pa0; *asw1 = pa1; *bsw0 = pb0; *bsw1 = pb1;
        __syncthreads();
        if (ci + 1 < 48) {
            int term = (ci+1) >> 4, kc = (ci+1) & 15;
            int ab = kau4[term] + kc*4, bb = kbu4[term] + kc*4;
            pa0 = arow ? arow[ab + lc0]   : z;
            pa1 = arow ? arow[ab + lc0+1] : z;
            pb0 = brow ? brow[bb + lc0]   : z;
            pb1 = brow ? brow[bb + lc0+1] : z;
        }
#pragma unroll
        for (int kk = 0; kk < 2; kk++) {
            int kp0 = kk*8 + tg;
            int kp1 = kp0 + 4;
            uint32_t afr[4][4];
#pragma unroll
            for (int mt = 0; mt < 4; mt++) {
                int r0 = wm + mt*16 + gq;
                afr[mt][0] = ldsw(As, r0,     kp0);
                afr[mt][1] = ldsw(As, r0 + 8, kp0);
                afr[mt][2] = ldsw(As, r0,     kp1);
                afr[mt][3] = ldsw(As, r0 + 8, kp1);
            }
            uint32_t bfr[4][2];
#pragma unroll
            for (int nt = 0; nt < 4; nt++) {
                int rn = wn + nt*8 + gq;
                bfr[nt][0] = ldsw(Bs, rn, kp0);
                bfr[nt][1] = ldsw(Bs, rn, kp1);
            }
#pragma unroll
            for (int mt = 0; mt < 4; mt++)
#pragma unroll
                for (int nt = 0; nt < 4; nt++)
                    mma16816(acc[mt][nt], afr[mt], bfr[nt]);
        }
    }

#pragma unroll
    for (int mt = 0; mt < 4; mt++) {
        int m0 = bm*128 + wm + mt*16 + gq;
        int m1 = m0 + 8;
        size_t row0 = 0, row1 = 0;
        bool v0 = m0 < Ml, v1 = m1 < Ml;
        if (v0) row0 = (size_t)(rowmap ? rowmap[m0] : m0);
        if (v1) row1 = (size_t)(rowmap ? rowmap[m1] : m1);
#pragma unroll
        for (int nt = 0; nt < 4; nt++) {
            int col = bn*128 + wn + nt*8 + tg*2;
            if (col >= N) continue;
            float bx = bias1[col], by = bias1[col+1];
            if (bias2) { bx += bias2[col]; by += bias2[col+1]; }
            if (v0) {
                float2 o = make_float2(acc[mt][nt][0] + bx, acc[mt][nt][1] + by);
                *(float2*)(C + row0*(size_t)ldc + col) = o;
            }
            if (v1) {
                float2 o = make_float2(acc[mt][nt][2] + bx, acc[mt][nt][3] + by);
                *(float2*)(C + row1*(size_t)ldc + col) = o;
            }
        }
    }
}

// ======================= fused persistent recurrence =======================
// smem layout (floats)
#define OW_DEC 0
#define OW_HH  2052
#define OW_IHC 10260
#define O_GH   18468
#define O_GATE 19492
#define O_PART 20516
#define O_STAGE 24612
#define RC_SMEMF 41028
#define RC_SMEMB (RC_SMEMF*4)

__device__ __forceinline__ void gridbar(int target) {
    __threadfence();
    __syncthreads();
    if (threadIdx.x == 0) {
        atomicAdd(&g_bar, 1);
        while (atomicAdd(&g_bar, 0) < target) { __nanosleep(64); }
    }
    __syncthreads();
    __threadfence();
}

// 16-row x 32-batch x K512 GEMM piece: part[ks][bl][r] partials
__device__ __forceinline__ void gemm16(const float* __restrict__ Ws,
                                       const float* __restrict__ stg,
                                       float* __restrict__ part, int tid)
{
    int bq4 = tid & 7, rq4 = (tid >> 3) & 3, ks = tid >> 5;
    float acc[4][4];
#pragma unroll
    for (int i = 0; i < 4; i++)
#pragma unroll
        for (int j = 0; j < 4; j++) acc[i][j] = 0.f;
    const float* hp = stg + (bq4*4)*513;
    const float* wp = Ws + (rq4*4)*513;
    int kbeg = ks*64;
#pragma unroll 4
    for (int k = kbeg; k < kbeg + 64; k++) {
        float hv0 = hp[k], hv1 = hp[513+k], hv2 = hp[1026+k], hv3 = hp[1539+k];
        float wv0 = wp[k], wv1 = wp[513+k], wv2 = wp[1026+k], wv3 = wp[1539+k];
        acc[0][0] = fmaf(hv0, wv0, acc[0][0]); acc[0][1] = fmaf(hv0, wv1, acc[0][1]);
        acc[0][2] = fmaf(hv0, wv2, acc[0][2]); acc[0][3] = fmaf(hv0, wv3, acc[0][3]);
        acc[1][0] = fmaf(hv1, wv0, acc[1][0]); acc[1][1] = fmaf(hv1, wv1, acc[1][1]);
        acc[1][2] = fmaf(hv1, wv2, acc[1][2]); acc[1][3] = fmaf(hv1, wv3, acc[1][3]);
        acc[2][0] = fmaf(hv2, wv0, acc[2][0]); acc[2][1] = fmaf(hv2, wv1, acc[2][1]);
        acc[2][2] = fmaf(hv2, wv2, acc[2][2]); acc[2][3] = fmaf(hv2, wv3, acc[2][3]);
        acc[3][0] = fmaf(hv3, wv0, acc[3][0]); acc[3][1] = fmaf(hv3, wv1, acc[3][1]);
        acc[3][2] = fmaf(hv3, wv2, acc[3][2]); acc[3][3] = fmaf(hv3, wv3, acc[3][3]);
    }
#pragma unroll
    for (int i = 0; i < 4; i++)
#pragma unroll
        for (int j = 0; j < 4; j++)
            part[ks*512 + (bq4*4+i)*16 + rq4*4 + j] = acc[i][j];
}

__global__ __launch_bounds__(NTHR)
void k_recur(const float* __restrict__ W_dec, const float* __restrict__ W_hh,
             const float* __restrict__ W_ih,
             const float* __restrict__ b_dec, const float* __restrict__ W_full,
             const float* __restrict__ b_full, float* __restrict__ out)
{
    extern __shared__ float sm[];
    __shared__ int sdl[BB];
    int tid = threadIdx.x;
    int j = blockIdx.x;

    // load declen
    if (tid < BB) sdl[tid] = g_declen[tid];

    // load weight slices: W_dec rows j*4..+4 ; W_hh / W_ih-ctx rows 512*g + j*4 + q (local r=g*4+q)
    for (int i = tid; i < 4*512; i += NTHR) {
        int r = i >> 9, k = i & 511;
        sm[OW_DEC + r*513 + k] = W_dec[(j*4 + r)*512 + k];
    }
    for (int i = tid; i < 16*512; i += NTHR) {
        int r = i >> 9, k = i & 511;
        int gr = 512*(r >> 2) + j*4 + (r & 3);
        sm[OW_HH  + r*513 + k] = W_hh[(size_t)gr*512 + k];
        sm[OW_IHC + r*513 + k] = W_ih[(size_t)gr*1024 + 512 + k];
    }
    __syncthreads();

    float* part  = sm + O_PART;
    float* stg   = sm + O_STAGE;
    float* gh_s  = sm + O_GH;
    float* gate_s= sm + O_GATE;

    int nbar = 0;
    for (int t = 0; t < TT; t++) {
        // ================= Phase A: gates_h + att2 =================
        for (int pb = 0; pb < 2; pb++) {
            int b0 = pb*32;
            // stage h[b0..b0+32]
            for (int i4 = tid; i4 < 32*128; i4 += NTHR) {
                int bl = i4 >> 7, k4 = (i4 & 127) << 2;
                float4 v = *(const float4*)(g_h + (size_t)(b0+bl)*512 + k4);
                float* d = stg + bl*513 + k4;
                d[0] = v.x; d[1] = v.y; d[2] = v.z; d[3] = v.w;
            }
            __syncthreads();
            // gates_h: 32b x 16r
            gemm16(sm + OW_HH, stg, part, tid);
            __syncthreads();
            for (int o = tid; o < 512; o += NTHR) {
                float s = 0.f;
#pragma unroll
                for (int ks = 0; ks < 8; ks++) s += part[ks*512 + o];
                gh_s[(b0 + (o >> 4))*16 + (o & 15)] = s;
            }
            __syncthreads();
            // att2: 32b x 4r, K-split 32
            {
                int bq4 = tid & 7, ksa = tid >> 3;
                float acc[4][4];
#pragma unroll
                for (int i = 0; i < 4; i++)
#pragma unroll
                    for (int q = 0; q < 4; q++) acc[i][q] = 0.f;
                const float* hp = stg + (bq4*4)*513;
                const float* wp = sm + OW_DEC;
                int kbeg = ksa*16;
#pragma unroll 4
                for (int k = kbeg; k < kbeg+16; k++) {
                    float hv0 = hp[k], hv1 = hp[513+k], hv2 = hp[1026+k], hv3 = hp[1539+k];
                    float w0 = wp[k], w1 = wp[513+k], w2 = wp[1026+k], w3 = wp[1539+k];
                    acc[0][0] = fmaf(hv0,w0,acc[0][0]); acc[0][1] = fmaf(hv0,w1,acc[0][1]);
                    acc[0][2] = fmaf(hv0,w2,acc[0][2]); acc[0][3] = fmaf(hv0,w3,acc[0][3]);
                    acc[1][0] = fmaf(hv1,w0,acc[1][0]); acc[1][1] = fmaf(hv1,w1,acc[1][1]);
                    acc[1][2] = fmaf(hv1,w2,acc[1][2]); acc[1][3] = fmaf(hv1,w3,acc[1][3]);
                    acc[2][0] = fmaf(hv2,w0,acc[2][0]); acc[2][1] = fmaf(hv2,w1,acc[2][1]);
                    acc[2][2] = fmaf(hv2,w2,acc[2][2]); acc[2][3] = fmaf(hv2,w3,acc[2][3]);
                    acc[3][0] = fmaf(hv3,w0,acc[3][0]); acc[3][1] = fmaf(hv3,w1,acc[3][1]);
                    acc[3][2] = fmaf(hv3,w2,acc[3][2]); acc[3][3] = fmaf(hv3,w3,acc[3][3]);
                }
#pragma unroll
                for (int i = 0; i < 4; i++)
#pragma unroll
                    for (int q = 0; q < 4; q++)
                        part[ksa*128 + (bq4*4+i)*4 + q] = acc[i][q];
            }
            __syncthreads();
            if (tid < 128) {
                int bl = tid >> 2, q = tid & 3;
                float s = 0.f;
#pragma unroll
                for (int ks = 0; ks < 32; ks++) s += part[ks*128 + tid];
                g_att2[(b0+bl)*512 + j*4 + q] = s;
            }
            __syncthreads();
        }
        gridbar((++nbar)*NCTA);

        // ================= Phase B: attention (CTAs 0..63) =================
        if (j < BB) {
            int b = j;
            bool active = t < sdl[b];
            float* wout = out + OFF_WEIGHTS + (size_t)(b*TT + t)*PP;
            if (!active) {
                for (int p = tid; p < PP; p += NTHR) wout[p] = 0.f;
            } else {
                float* s_att2 = stg;
                float* s_wf   = stg + 512;
                float* s_e    = stg + 1024;
                float* s_red  = stg + 1248;
                float* rbuf   = stg + 1280;
                for (int a = tid; a < AA; a += NTHR) {
                    s_att2[a] = g_att2[b*512 + a] + b_dec[a];
                    s_wf[a] = W_full[a];
                }
                __syncthreads();
                int lane = tid & 31, w = tid >> 5;
                const float* ea = g_encatt + (size_t)b * PP * AA;
                for (int p = w; p < PP; p += 8) {
                    const float* row = ea + (size_t)p * AA;
                    float sum = 0.f;
                    for (int a = lane; a < AA; a += 32)
                        sum += fmaxf(row[a] + s_att2[a], 0.f) * s_wf[a];
#pragma unroll
                    for (int o = 16; o; o >>= 1) sum += __shfl_xor_sync(0xffffffffu, sum, o);
                    if (lane == 0) s_e[p] = sum + b_full[0];
                }
                __syncthreads();
                float m = -1e30f;
                if (tid < PP) m = s_e[tid];
#pragma unroll
                for (int o = 16; o; o >>= 1) m = fmaxf(m, __shfl_xor_sync(0xffffffffu, m, o));
                if (lane == 0) s_red[w] = m;
                __syncthreads();
                float mx = s_red[0];
#pragma unroll
                for (int i = 1; i < 8; i++) mx = fmaxf(mx, s_red[i]);
                float ev = 0.f;
                if (tid < PP) ev = expf(s_e[tid] - mx);
                float sv = ev;
#pragma unroll
                for (int o = 16; o; o >>= 1) sv += __shfl_xor_sync(0xffffffffu, sv, o);
                __syncthreads();
                if (lane == 0) s_red[w] = sv;
                __syncthreads();
                float tot = 0.f;
#pragma unroll
                for (int i = 0; i < 8; i++) tot += s_red[i];
                float inv = 1.f / tot;
                if (tid < PP) {
                    float al = ev * inv;
                    s_e[tid] = al;
                    wout[tid] = al;
                }
                __syncthreads();
                // ctx: thread = (hq 64) x (pc 4), 8 floats per hq
                int hq = tid & 63, pc = tid >> 6;
                const float4* fb4 = (const float4*)(g_feats + (size_t)b * PP * HH);
                float4 a0 = make_float4(0,0,0,0), a1 = make_float4(0,0,0,0);
                for (int p = pc; p < PP; p += 4) {
                    float al = s_e[p];
                    float4 v0 = fb4[p*128 + hq*2];
                    float4 v1 = fb4[p*128 + hq*2 + 1];
                    a0.x = fmaf(al, v0.x, a0.x); a0.y = fmaf(al, v0.y, a0.y);
                    a0.z = fmaf(al, v0.z, a0.z); a0.w = fmaf(al, v0.w, a0.w);
                    a1.x = fmaf(al, v1.x, a1.x); a1.y = fmaf(al, v1.y, a1.y);
                    a1.z = fmaf(al, v1.z, a1.z); a1.w = fmaf(al, v1.w, a1.w);
                }
                float* rb = rbuf + pc*512 + hq*8;
                rb[0]=a0.x; rb[1]=a0.y; rb[2]=a0.z; rb[3]=a0.w;
                rb[4]=a1.x; rb[5]=a1.y; rb[6]=a1.z; rb[7]=a1.w;
                __syncthreads();
                for (int o = tid; o < 512; o += NTHR) {
                    float s = rbuf[o] + rbuf[512+o] + rbuf[1024+o] + rbuf[1536+o];
                    g_ctx[b*512 + o] = s;
                }
            }
        }
        gridbar((++nbar)*NCTA);

        // ================= Phase C: gates_ctx + lstm =================
        for (int pb = 0; pb < 2; pb++) {
            int b0 = pb*32;
            for (int i4 = tid; i4 < 32*128; i4 += NTHR) {
                int bl = i4 >> 7, k4 = (i4 & 127) << 2;
                float4 v = *(const float4*)(g_ctx + (size_t)(b0+bl)*512 + k4);
                float* d = stg + bl*513 + k4;
                d[0] = v.x; d[1] = v.y; d[2] = v.z; d[3] = v.w;
            }
            __syncthreads();
            gemm16(sm + OW_IHC, stg, part, tid);
            __syncthreads();
            for (int o = tid; o < 512; o += NTHR) {
                int bl = o >> 4, r = o & 15;
                float s = 0.f;
#pragma unroll
                for (int ks = 0; ks < 8; ks++) s += part[ks*512 + o];
                int b = b0 + bl;
                int gr = 512*(r >> 2) + j*4 + (r & 3);
                gate_s[b*16 + r] = s + gh_s[b*16 + r] + g_embg[(size_t)(b*TT + t)*NG + gr];
            }
            __syncthreads();
        }
        // lstm pointwise: 64 b x 4 k
        {
            int b = tid >> 2, q = tid & 3;
            int k = j*4 + q;
            float gi = gate_s[b*16 + q];
            float gf = gate_s[b*16 + 4 + q];
            float gg = gate_s[b*16 + 8 + q];
            float go = gate_s[b*16 + 12 + q];
            float ig = 1.f / (1.f + expf(-gi));
            float fg = 1.f / (1.f + expf(-gf));
            float gv = tanhf(gg);
            float og = 1.f / (1.f + expf(-go));
            float c_new = fg * g_c[b*512 + k] + ig * gv;
            float h_new = og * tanhf(c_new);
            g_hall[(size_t)(b*TT + t)*512 + k] = h_new;
            if (t < sdl[b]) { g_h[b*512 + k] = h_new; g_c[b*512 + k] = c_new; }
        }
        gridbar((++nbar)*NCTA);
    }
}

// ======================= launch =======================
extern "C" void kernel_launch(void* const* d_in, const int* in_sizes, int n_in,
                              void* d_out, int out_size) {
    const float* imf     = (const float*)d_in[0];
    const int*   caps    = (const int*)  d_in[1];
    const int*   caplens = (const int*)  d_in[2];
    const float* emb     = (const float*)d_in[3];
    const float* W_ih    = (const float*)d_in[4];
    const float* W_hh    = (const float*)d_in[5];
    const float* b_ih    = (const float*)d_in[6];
    const float* b_hh    = (const float*)d_in[7];
    const float* W_enc   = (const float*)d_in[8];
    const float* b_enc   = (const float*)d_in[9];
    const float* W_dec   = (const float*)d_in[10];
    const float* b_dec   = (const float*)d_in[11];
    const float* W_full  = (const float*)d_in[12];
    const float* b_full  = (const float*)d_in[13];
    const float* W_score = (const float*)d_in[14];
    const float* b_score = (const float*)d_in[15];
    float* out = (float*)d_out;

    float *p_feats, *p_encatt, *p_embT, *p_embg, *p_hall;
    int *p_act;
    __nv_bfloat16 *p_feats2, *p_embT2, *p_hall2, *p_Wenc2, *p_Wih2, *p_Wsc2;
    cudaGetSymbolAddress((void**)&p_feats,  g_feats);
    cudaGetSymbolAddress((void**)&p_encatt, g_encatt);
    cudaGetSymbolAddress((void**)&p_embT,   g_embT);
    cudaGetSymbolAddress((void**)&p_embg,   g_embg);
    cudaGetSymbolAddress((void**)&p_hall,   g_hall);
    cudaGetSymbolAddress((void**)&p_act,    g_act);
    cudaGetSymbolAddress((void**)&p_feats2, g_feats2);
    cudaGetSymbolAddress((void**)&p_embT2,  g_embT2);
    cudaGetSymbolAddress((void**)&p_hall2,  g_hall2);
    cudaGetSymbolAddress((void**)&p_Wenc2,  g_Wenc2);
    cudaGetSymbolAddress((void**)&p_Wih2,   g_Wih2);
    cudaGetSymbolAddress((void**)&p_Wsc2,   g_Wsc2);

    cudaFuncSetAttribute(k_recur, cudaFuncAttributeMaxDynamicSharedMemorySize, RC_SMEMB);

    // prep
    k_sort<<<1, BB>>>(caplens, caps, out);
    k_gather_feats<<<(BB*PP*HH/4 + 255)/256, 256>>>(imf);
    k_gather_emb<<<(BB*TT*EE/4 + 255)/256, 256>>>(caps, emb);
    k_init<<<(BB*HH + 255)/256, 256>>>();
    k_zero4<<<(N_SCORES/4 + 255)/256, 256>>>(out, N_SCORES/4);

    // bf16 hi/lo conversions
    k_cvt_hilo<<<(BB*PP*512 + 255)/256, 256>>>(p_feats, HH, p_feats2, BB*PP);
    k_cvt_hilo<<<(BB*TT*512 + 255)/256, 256>>>(p_embT, EE, p_embT2, BB*TT);
    k_cvt_hilo<<<(AA*512 + 255)/256, 256>>>(W_enc, HH, p_Wenc2, AA);
    k_cvt_hilo<<<(NG*512 + 255)/256, 256>>>(W_ih, 1024, p_Wih2, NG);
    k_cvt_hilo<<<(VV*512 + 255)/256, 256>>>(W_score, HH, p_Wsc2, VV);

    // enc_att = feats @ W_enc^T + b_enc   (M=12544, N=512)
    hgemm<<<dim3((BB*PP + 127)/128, (AA + 127)/128), 256>>>(
        p_feats2, p_Wenc2, BB*PP, AA, AA, b_enc, nullptr, p_encatt, nullptr, 0);
    // G_emb = emb @ W_ih[:, :512]^T + b_ih + b_hh  (active rows)
    hgemm<<<dim3((BB*TT + 127)/128, (NG + 127)/128), 256>>>(
        p_embT2, p_Wih2, BB*TT, NG, NG, b_ih, b_hh, p_embg, p_act, 1);

    // fused persistent recurrence (49 steps)
    k_recur<<<NCTA, NTHR, RC_SMEMB>>>(W_dec, W_hh, W_ih, b_dec, W_full, b_full, out);

    // scores = h_all @ W_score^T + b_score (active rows)
    k_cvt_hilo<<<(BB*TT*512 + 255)/256, 256>>>(p_hall, HH, p_hall2, BB*TT);
    hgemm<<<dim3((BB*TT + 127)/128, (VV + 127)/128), 256>>>(
        p_hall2, p_Wsc2, BB*TT, VV, VV, b_score, nullptr, out, p_act, 1);
}

// round 5
// speedup vs baseline: 1.4693x; 1.0180x over previous
#include <cuda_runtime.h>
#include <cuda_bf16.h>
#include <cstdint>
#include <math.h>

#define BB 64
#define PP 196
#define HH 512
#define EE 512
#define AA 512
#define VV 10000
#define MAXCAP 50
#define TT 49
#define NG 2048   // 4*H

// output layout (float32): scores (B,T,V), caps_s (B,50), decode_lengths (B,), weights (B,T,P), sort_ind (B,)
#define N_SCORES   (BB*TT*VV)
#define OFF_CAPS   (N_SCORES)
#define OFF_DECLEN (OFF_CAPS + BB*MAXCAP)
#define OFF_WEIGHTS (OFF_DECLEN + BB)
#define OFF_SORT   (OFF_WEIGHTS + BB*TT*PP)

#define NCTA 128
#define NTHR 256

// ======================= scratch =======================
__device__ float g_feats[BB*PP*HH];
__device__ float g_encatt[BB*PP*AA];
__device__ float g_embg[BB*TT*NG];
__device__ float g_hall[BB*TT*HH];
__device__ float g_h[BB*HH];
__device__ float g_c[BB*HH];
__device__ float g_att2[BB*AA];
__device__ float g_ctx[BB*HH];
__device__ int   g_sortidx[BB];
__device__ int   g_declen[BB];
__device__ int   g_act[BB*TT];
__device__ int   g_nact;
__device__ int   g_bar;

// bf16 hi/lo packed [rows][1024]: cols 0-511 hi, 512-1023 lo
__device__ __nv_bfloat16 g_feats2[BB*PP*1024];
__device__ __nv_bfloat16 g_embT2[BB*TT*1024];
__device__ __nv_bfloat16 g_hall2[BB*TT*1024];
__device__ __nv_bfloat16 g_Wenc2[AA*1024];
__device__ __nv_bfloat16 g_Wih2[NG*1024];
__device__ __nv_bfloat16 g_Wsc2[VV*1024];

// ======================= helpers =======================
__device__ __forceinline__ void mma16816(float* d, const uint32_t* a, const uint32_t* b) {
    asm volatile("mma.sync.aligned.m16n8k16.row.col.f32.bf16.bf16.f32 "
        "{%0,%1,%2,%3}, {%4,%5,%6,%7}, {%8,%9}, {%0,%1,%2,%3};"
        : "+f"(d[0]), "+f"(d[1]), "+f"(d[2]), "+f"(d[3])
        : "r"(a[0]), "r"(a[1]), "r"(a[2]), "r"(a[3]), "r"(b[0]), "r"(b[1]));
}
// swizzled tile (rows of 32 bf16 = 64B): load 2 bf16 at (row, kpair)
__device__ __forceinline__ uint32_t ldsw(const __nv_bfloat16* s, int row, int kpair) {
    int byte = row*64 + ((((kpair >> 2) ^ ((row >> 1) & 3))) << 4) + ((kpair & 3) << 2);
    return *(const uint32_t*)((const char*)s + byte);
}
__device__ __forceinline__ uint32_t ldsw2(const char* s, int row, int kpair) {
    int byte = row*64 + ((((kpair >> 2) ^ ((row >> 1) & 3))) << 4) + ((kpair & 3) << 2);
    return *(const uint32_t*)(s + byte);
}
// store bf16x2 at (r, c even 0..31)
__device__ __forceinline__ void stsw2(char* s, int r, int c, uint32_t v) {
    int byte = r*64 + ((((c >> 3) ^ ((r >> 1) & 3))) << 4) + (c & 7)*2;
    *(uint32_t*)(s + byte) = v;
}
__device__ __forceinline__ void cvt_hilo2(float2 v, uint32_t& hp, uint32_t& lp) {
    __nv_bfloat16 h0 = __float2bfloat16(v.x), h1 = __float2bfloat16(v.y);
    float l0 = v.x - __bfloat162float(h0), l1 = v.y - __bfloat162float(h1);
    __nv_bfloat16 b0 = __float2bfloat16(l0), b1 = __float2bfloat16(l1);
    hp = (uint32_t)__bfloat16_as_ushort(h0) | ((uint32_t)__bfloat16_as_ushort(h1) << 16);
    lp = (uint32_t)__bfloat16_as_ushort(b0) | ((uint32_t)__bfloat16_as_ushort(b1) << 16);
}

// ======================= prep kernels =======================
__global__ void k_sort(const int* __restrict__ caplens, const int* __restrict__ caps,
                       float* __restrict__ out) {
    __shared__ int s_sort[BB];
    if (threadIdx.x == 0) {
        int cl[BB];
        for (int i = 0; i < BB; i++) cl[i] = caplens[i];
        int r = 0;
        for (int v = MAXCAP; v >= 0 && r < BB; v--)
            for (int i = 0; i < BB; i++)
                if (cl[i] == v) { g_sortidx[r] = i; s_sort[r] = i; r++; }
        int na = 0;
        for (int b = 0; b < BB; b++) {
            int dl = cl[g_sortidx[b]] - 1;
            g_declen[b] = dl;
            out[OFF_DECLEN + b] = (float)dl;
            out[OFF_SORT + b]   = (float)g_sortidx[b];
            for (int t = 0; t < dl; t++) g_act[na++] = b*TT + t;
        }
        g_nact = na;
    }
    __syncthreads();
    int b = threadIdx.x;
    int src = s_sort[b];
    for (int t = 0; t < MAXCAP; t++)
        out[OFF_CAPS + b*MAXCAP + t] = (float)caps[src*MAXCAP + t];
}

// fused gather + hi/lo conversion + zero + init
#define S0 (BB*PP*512)
#define S1 (BB*TT*512)
#define S2 (AA*512)
#define S3 (NG*512)
#define S4 (VV*512)
#define S5 (N_SCORES/4)
#define S6 (BB*HH)
__global__ void k_cvt_all(const float* __restrict__ imf, const int* __restrict__ caps,
                          const float* __restrict__ emb, const float* __restrict__ W_enc,
                          const float* __restrict__ W_ih, const float* __restrict__ W_score,
                          float* __restrict__ out)
{
    const int total = S0+S1+S2+S3+S4+S5+S6;
    for (int i = blockIdx.x*blockDim.x + threadIdx.x; i < total; i += gridDim.x*blockDim.x) {
        int x = i;
        if (x < S0) {
            int row = x >> 9, c = x & 511;
            int b = row / PP, p = row - b*PP;
            float v = imf[((size_t)g_sortidx[b]*PP + p)*512 + c];
            g_feats[(size_t)row*512 + c] = v;
            __nv_bfloat16 hi = __float2bfloat16(v);
            g_feats2[(size_t)row*1024 + c] = hi;
            g_feats2[(size_t)row*1024 + 512 + c] = __float2bfloat16(v - __bfloat162float(hi));
            continue;
        }
        x -= S0;
        if (x < S1) {
            int row = x >> 9, c = x & 511;
            int b = row / TT, t = row - b*TT;
            int tok = caps[g_sortidx[b]*MAXCAP + t];
            float v = emb[(size_t)tok*512 + c];
            __nv_bfloat16 hi = __float2bfloat16(v);
            g_embT2[(size_t)row*1024 + c] = hi;
            g_embT2[(size_t)row*1024 + 512 + c] = __float2bfloat16(v - __bfloat162float(hi));
            continue;
        }
        x -= S1;
        if (x < S2) {
            int r = x >> 9, c = x & 511;
            float v = W_enc[x];
            __nv_bfloat16 hi = __float2bfloat16(v);
            g_Wenc2[(size_t)r*1024 + c] = hi;
            g_Wenc2[(size_t)r*1024 + 512 + c] = __float2bfloat16(v - __bfloat162float(hi));
            continue;
        }
        x -= S2;
        if (x < S3) {
            int r = x >> 9, c = x & 511;
            float v = W_ih[(size_t)r*1024 + c];
            __nv_bfloat16 hi = __float2bfloat16(v);
            g_Wih2[(size_t)r*1024 + c] = hi;
            g_Wih2[(size_t)r*1024 + 512 + c] = __float2bfloat16(v - __bfloat162float(hi));
            continue;
        }
        x -= S3;
        if (x < S4) {
            int r = x >> 9, c = x & 511;
            float v = W_score[x];
            __nv_bfloat16 hi = __float2bfloat16(v);
            g_Wsc2[(size_t)r*1024 + c] = hi;
            g_Wsc2[(size_t)r*1024 + 512 + c] = __float2bfloat16(v - __bfloat162float(hi));
            continue;
        }
        x -= S4;
        if (x < S5) {
            ((float4*)out)[x] = make_float4(0.f, 0.f, 0.f, 0.f);
            continue;
        }
        x -= S5;
        g_h[x] = 0.f; g_c[x] = 0.f;
        if (x == 0) g_bar = 0;
    }
}

// ======================= mma.sync bf16x3 GEMM body =======================
__device__ __forceinline__ void hgemm_body(
    int bm, int bn,
    const __nv_bfloat16* __restrict__ A2, const __nv_bfloat16* __restrict__ B2,
    int M, int N, int ldc,
    const float* __restrict__ bias1, const float* __restrict__ bias2,
    float* __restrict__ C, const int* __restrict__ rowmap, int use_nact,
    __nv_bfloat16* As, __nv_bfloat16* Bs)
{
    int tid = threadIdx.x;
    int Ml = use_nact ? g_nact : M;
    if (bm*128 >= Ml) return;

    int lrow = tid >> 1;
    int lc0 = (tid & 1) * 2;
    int gm = bm*128 + lrow;
    const uint4* arow = nullptr;
    if (gm < Ml) { int r = rowmap ? rowmap[gm] : gm; arow = (const uint4*)(A2 + (size_t)r*1024); }
    int gn = bn*128 + lrow;
    const uint4* brow = (gn < N) ? (const uint4*)(B2 + (size_t)gn*1024) : nullptr;

    int swz = (lrow >> 1) & 3;
    uint4* asw0 = (uint4*)(As + lrow*32) + (lc0 ^ swz);
    uint4* asw1 = (uint4*)(As + lrow*32) + ((lc0+1) ^ swz);
    uint4* bsw0 = (uint4*)(Bs + lrow*32) + (lc0 ^ swz);
    uint4* bsw1 = (uint4*)(Bs + lrow*32) + ((lc0+1) ^ swz);

    int lane = tid & 31, wid = tid >> 5;
    int wm = (wid >> 2) * 64;
    int wn = (wid & 3) * 32;
    int gq = lane >> 2, tg = lane & 3;

    float acc[4][4][4];
#pragma unroll
    for (int mt = 0; mt < 4; mt++)
#pragma unroll
        for (int nt = 0; nt < 4; nt++)
#pragma unroll
            for (int r = 0; r < 4; r++) acc[mt][nt][r] = 0.f;

    const uint4 z = make_uint4(0,0,0,0);
    uint4 pa0, pa1, pb0, pb1;
    const int kau4[3] = {0, 0, 64};
    const int kbu4[3] = {0, 64, 0};
    pa0 = arow ? arow[lc0]   : z;
    pa1 = arow ? arow[lc0+1] : z;
    pb0 = brow ? brow[lc0]   : z;
    pb1 = brow ? brow[lc0+1] : z;

    for (int ci = 0; ci < 48; ci++) {
        __syncthreads();
        *asw0 = pa0; *asw1 = pa1; *bsw0 = pb0; *bsw1 = pb1;
        __syncthreads();
        if (ci + 1 < 48) {
            int term = (ci+1) >> 4, kc = (ci+1) & 15;
            int ab = kau4[term] + kc*4, bb = kbu4[term] + kc*4;
            pa0 = arow ? arow[ab + lc0]   : z;
            pa1 = arow ? arow[ab + lc0+1] : z;
            pb0 = brow ? brow[bb + lc0]   : z;
            pb1 = brow ? brow[bb + lc0+1] : z;
        }
#pragma unroll
        for (int kk = 0; kk < 2; kk++) {
            int kp0 = kk*8 + tg;
            int kp1 = kp0 + 4;
            uint32_t afr[4][4];
#pragma unroll
            for (int mt = 0; mt < 4; mt++) {
                int r0 = wm + mt*16 + gq;
                afr[mt][0] = ldsw(As, r0,     kp0);
                afr[mt][1] = ldsw(As, r0 + 8, kp0);
                afr[mt][2] = ldsw(As, r0,     kp1);
                afr[mt][3] = ldsw(As, r0 + 8, kp1);
            }
            uint32_t bfr[4][2];
#pragma unroll
            for (int nt = 0; nt < 4; nt++) {
                int rn = wn + nt*8 + gq;
                bfr[nt][0] = ldsw(Bs, rn, kp0);
                bfr[nt][1] = ldsw(Bs, rn, kp1);
            }
#pragma unroll
            for (int mt = 0; mt < 4; mt++)
#pragma unroll
                for (int nt = 0; nt < 4; nt++)
                    mma16816(acc[mt][nt], afr[mt], bfr[nt]);
        }
    }

#pragma unroll
    for (int mt = 0; mt < 4; mt++) {
        int m0 = bm*128 + wm + mt*16 + gq;
        int m1 = m0 + 8;
        size_t row0 = 0, row1 = 0;
        bool v0 = m0 < Ml, v1 = m1 < Ml;
        if (v0) row0 = (size_t)(rowmap ? rowmap[m0] : m0);
        if (v1) row1 = (size_t)(rowmap ? rowmap[m1] : m1);
#pragma unroll
        for (int nt = 0; nt < 4; nt++) {
            int col = bn*128 + wn + nt*8 + tg*2;
            if (col >= N) continue;
            float bx = bias1[col], by = bias1[col+1];
            if (bias2) { bx += bias2[col]; by += bias2[col+1]; }
            if (v0) {
                float2 o = make_float2(acc[mt][nt][0] + bx, acc[mt][nt][1] + by);
                *(float2*)(C + row0*(size_t)ldc + col) = o;
            }
            if (v1) {
                float2 o = make_float2(acc[mt][nt][2] + bx, acc[mt][nt][3] + by);
                *(float2*)(C + row1*(size_t)ldc + col) = o;
            }
        }
    }
}

// fused launch: enc_att (98x4=392 blocks) + G_emb (25x16=400 blocks)
__global__ __launch_bounds__(256)
void k_gemm_pair(const float* __restrict__ b_enc, const float* __restrict__ b_ih,
                 const float* __restrict__ b_hh)
{
    __shared__ __align__(16) __nv_bfloat16 As[128*32];
    __shared__ __align__(16) __nv_bfloat16 Bs[128*32];
    int idx = blockIdx.x;
    if (idx < 392) {
        hgemm_body(idx >> 2, idx & 3, g_feats2, g_Wenc2, BB*PP, AA, AA,
                   b_enc, nullptr, g_encatt, nullptr, 0, As, Bs);
    } else {
        idx -= 392;
        hgemm_body(idx >> 4, idx & 15, g_embT2, g_Wih2, BB*TT, NG, NG,
                   b_ih, b_hh, g_embg, g_act, 1, As, Bs);
    }
}

__global__ __launch_bounds__(256)
void k_gemm_scores(const float* __restrict__ b_score, float* __restrict__ out)
{
    __shared__ __align__(16) __nv_bfloat16 As[128*32];
    __shared__ __align__(16) __nv_bfloat16 Bs[128*32];
    hgemm_body(blockIdx.x, blockIdx.y, g_hall2, g_Wsc2, BB*TT, VV, VV,
               b_score, nullptr, out, g_act, 1, As, Bs);
}

__global__ void k_cvt_hall() {
    int i = blockIdx.x*blockDim.x + threadIdx.x;
    if (i >= BB*TT*512) return;
    int r = i >> 9, c = i & 511;
    float v = g_hall[(size_t)r*512 + c];
    __nv_bfloat16 hi = __float2bfloat16(v);
    g_hall2[(size_t)r*1024 + c] = hi;
    g_hall2[(size_t)r*1024 + 512 + c] = __float2bfloat16(v - __bfloat162float(hi));
}

// ======================= fused persistent recurrence (mma gates) =======================
// smem byte offsets
#define WHH_OFF  0
#define WIHC_OFF 32768
#define WDEC_OFF 65536
#define HT_OFF   81920
#define PART_OFF 147456
#define GH_OFF   155648
#define SM_TOTAL 159744

__device__ __forceinline__ void gridbar(int nbar) {
    __syncthreads();
    if (threadIdx.x == 0) {
        int target = nbar * NCTA;
        int* p = &g_bar;
        asm volatile("red.release.gpu.global.add.s32 [%0], 1;" :: "l"(p) : "memory");
        int v;
        do {
            asm volatile("ld.acquire.gpu.global.s32 %0, [%1];" : "=r"(v) : "l"(p) : "memory");
        } while (v < target);
    }
    __syncthreads();
}

// stage 32 rows (b0..b0+31) of fp32[512] into hi/lo swizzled tiles at HTp
__device__ __forceinline__ void stage32(const float* __restrict__ src, int b0, char* HTp, int tid) {
    for (int i = tid; i < 32*256; i += NTHR) {
        int r = i >> 8, kp = i & 255, k = kp*2;
        float2 v = *(const float2*)(src + (size_t)(b0+r)*512 + k);
        uint32_t hp, lp;
        cvt_hilo2(v, hp, lp);
        int kt = k >> 5, c = k & 31;
        stsw2(HTp + kt*2048, r, c, hp);
        stsw2(HTp + (16+kt)*2048, r, c, lp);
    }
}

// gates mma: M=32 (h tiles), N=16 (weight tiles), K=512, 3 hi/lo terms -> part[2][32][16]
__device__ __forceinline__ void gates_mma(const char* HT_, const char* WB, float* part,
                                          int wid, int lane) {
    int gq = lane >> 2, tg = lane & 3;
    int mh = (wid & 1)*16, nh = ((wid >> 1) & 1)*8, ks = wid >> 2;
    float acc[4] = {0.f, 0.f, 0.f, 0.f};
    for (int kt = ks*8; kt < ks*8 + 8; kt++) {
        const char* ah = HT_ + kt*2048;
        const char* al = HT_ + (16+kt)*2048;
        const char* bh = WB + kt*1024;
        const char* bl = WB + (16+kt)*1024;
#pragma unroll
        for (int kk = 0; kk < 2; kk++) {
            int kp0 = kk*8 + tg, kp1 = kp0 + 4;
            uint32_t Ah[4] = {ldsw2(ah, mh+gq, kp0), ldsw2(ah, mh+8+gq, kp0),
                              ldsw2(ah, mh+gq, kp1), ldsw2(ah, mh+8+gq, kp1)};
            uint32_t Al[4] = {ldsw2(al, mh+gq, kp0), ldsw2(al, mh+8+gq, kp0),
                              ldsw2(al, mh+gq, kp1), ldsw2(al, mh+8+gq, kp1)};
            uint32_t Bh[2] = {ldsw2(bh, nh+gq, kp0), ldsw2(bh, nh+gq, kp1)};
            uint32_t Bl[2] = {ldsw2(bl, nh+gq, kp0), ldsw2(bl, nh+gq, kp1)};
            mma16816(acc, Ah, Bh);
            mma16816(acc, Ah, Bl);
            mma16816(acc, Al, Bh);
        }
    }
    int m0 = mh + gq, n0 = nh + tg*2;
    part[ks*512 + m0*16 + n0]     = acc[0];
    part[ks*512 + m0*16 + n0+1]   = acc[1];
    part[ks*512 + (m0+8)*16 + n0]   = acc[2];
    part[ks*512 + (m0+8)*16 + n0+1] = acc[3];
}

// att2 mma: M=32, N=8 (4 real W_dec rows + 4 zero), K=512 -> part2[4][32][8]
__device__ __forceinline__ void att2_mma(const char* HT_, const char* WD, float* part2,
                                         int wid, int lane) {
    int gq = lane >> 2, tg = lane & 3;
    int mh = (wid & 1)*16, ks = wid >> 1;
    float acc[4] = {0.f, 0.f, 0.f, 0.f};
    for (int kt = ks*4; kt < ks*4 + 4; kt++) {
        const char* ah = HT_ + kt*2048;
        const char* al = HT_ + (16+kt)*2048;
        const char* bh = WD + kt*512;
        const char* bl = WD + (16+kt)*512;
#pragma unroll
        for (int kk = 0; kk < 2; kk++) {
            int kp0 = kk*8 + tg, kp1 = kp0 + 4;
            uint32_t Ah[4] = {ldsw2(ah, mh+gq, kp0), ldsw2(ah, mh+8+gq, kp0),
                              ldsw2(ah, mh+gq, kp1), ldsw2(ah, mh+8+gq, kp1)};
            uint32_t Al[4] = {ldsw2(al, mh+gq, kp0), ldsw2(al, mh+8+gq, kp0),
                              ldsw2(al, mh+gq, kp1), ldsw2(al, mh+8+gq, kp1)};
            uint32_t Bh[2] = {ldsw2(bh, gq, kp0), ldsw2(bh, gq, kp1)};
            uint32_t Bl[2] = {ldsw2(bl, gq, kp0), ldsw2(bl, gq, kp1)};
            mma16816(acc, Ah, Bh);
            mma16816(acc, Ah, Bl);
            mma16816(acc, Al, Bh);
        }
    }
    int m0 = mh + gq, n0 = tg*2;
    part2[ks*256 + m0*8 + n0]     = acc[0];
    part2[ks*256 + m0*8 + n0+1]   = acc[1];
    part2[ks*256 + (m0+8)*8 + n0]   = acc[2];
    part2[ks*256 + (m0+8)*8 + n0+1] = acc[3];
}

__global__ __launch_bounds__(NTHR)
void k_recur(const float* __restrict__ W_dec, const float* __restrict__ W_hh,
             const float* __restrict__ W_ih,
             const float* __restrict__ b_dec, const float* __restrict__ W_full,
             const float* __restrict__ b_full, float* __restrict__ out)
{
    extern __shared__ float sm[];
    char* smc = (char*)sm;
    __shared__ int sdl[BB];
    int tid = threadIdx.x, lane = tid & 31, wid = tid >> 5;
    int j = blockIdx.x;

    if (tid < BB) sdl[tid] = g_declen[tid];

    // convert weight slices to swizzled bf16 hi/lo tiles (once)
    for (int i = tid; i < 16*256; i += NTHR) {
        int r = i >> 8, kp = i & 255, k = kp*2;
        int gr = 512*(r >> 2) + j*4 + (r & 3);
        float2 w1 = *(const float2*)(W_hh + (size_t)gr*512 + k);
        float2 w2 = *(const float2*)(W_ih + (size_t)gr*1024 + 512 + k);
        uint32_t hp, lp;
        int kt = k >> 5, c = k & 31;
        cvt_hilo2(w1, hp, lp);
        stsw2(smc + WHH_OFF + kt*1024, r, c, hp);
        stsw2(smc + WHH_OFF + (16+kt)*1024, r, c, lp);
        cvt_hilo2(w2, hp, lp);
        stsw2(smc + WIHC_OFF + kt*1024, r, c, hp);
        stsw2(smc + WIHC_OFF + (16+kt)*1024, r, c, lp);
    }
    for (int i = tid; i < 8*256; i += NTHR) {
        int r = i >> 8, kp = i & 255, k = kp*2;
        float2 w = (r < 4) ? *(const float2*)(W_dec + (size_t)(j*4+r)*512 + k)
                           : make_float2(0.f, 0.f);
        uint32_t hp, lp;
        cvt_hilo2(w, hp, lp);
        int kt = k >> 5, c = k & 31;
        stsw2(smc + WDEC_OFF + kt*512, r, c, hp);
        stsw2(smc + WDEC_OFF + (16+kt)*512, r, c, lp);
    }
    __syncthreads();

    float* part  = (float*)(smc + PART_OFF);
    float* part2 = part + 1024;
    float* gh    = (float*)(smc + GH_OFF);

    int nbar = 0;
    for (int t = 0; t < TT; t++) {
        // ---- Phase A: gates_h + att2 (mma) ----
        for (int pb = 0; pb < 2; pb++) {
            int b0 = pb*32;
            stage32(g_h, b0, smc + HT_OFF, tid);
            __syncthreads();
            gates_mma(smc + HT_OFF, smc + WHH_OFF, part, wid, lane);
            att2_mma(smc + HT_OFF, smc + WDEC_OFF, part2, wid, lane);
            __syncthreads();
            for (int o = tid; o < 512; o += NTHR)
                gh[(b0 + (o >> 4))*16 + (o & 15)] = part[o] + part[512 + o];
            if (tid < 128) {
                int m = tid >> 2, q = tid & 3;
                float s = part2[m*8+q] + part2[256 + m*8+q] + part2[512 + m*8+q] + part2[768 + m*8+q];
                g_att2[(b0+m)*512 + j*4 + q] = s;
            }
            __syncthreads();
        }
        gridbar(++nbar);

        // ---- Phase B: attention (CTAs 0..63) ----
        if (j < BB) {
            int b = j;
            bool active = t < sdl[b];
            float* wout = out + OFF_WEIGHTS + (size_t)(b*TT + t)*PP;
            float* att = (float*)(smc + HT_OFF);
            float* s_att2 = att;
            float* s_wf   = att + 512;
            float* s_e    = att + 1024;
            float* s_red  = att + 1248;
            float* rbuf   = att + 1280;
            if (!active) {
                for (int p = tid; p < PP; p += NTHR) wout[p] = 0.f;
            } else {
                for (int a = tid; a < AA; a += NTHR) {
                    s_att2[a] = g_att2[b*512 + a] + b_dec[a];
                    s_wf[a] = W_full[a];
                }
                __syncthreads();
                const float* ea = g_encatt + (size_t)b * PP * AA;
                for (int p = wid; p < PP; p += 8) {
                    const float* row = ea + (size_t)p * AA;
                    float sum = 0.f;
                    for (int a = lane; a < AA; a += 32)
                        sum += fmaxf(row[a] + s_att2[a], 0.f) * s_wf[a];
#pragma unroll
                    for (int o = 16; o; o >>= 1) sum += __shfl_xor_sync(0xffffffffu, sum, o);
                    if (lane == 0) s_e[p] = sum + b_full[0];
                }
                __syncthreads();
                float m = -1e30f;
                if (tid < PP) m = s_e[tid];
#pragma unroll
                for (int o = 16; o; o >>= 1) m = fmaxf(m, __shfl_xor_sync(0xffffffffu, m, o));
                if (lane == 0) s_red[wid] = m;
                __syncthreads();
                float mx = s_red[0];
#pragma unroll
                for (int i = 1; i < 8; i++) mx = fmaxf(mx, s_red[i]);
                float ev = 0.f;
                if (tid < PP) ev = expf(s_e[tid] - mx);
                float sv = ev;
#pragma unroll
                for (int o = 16; o; o >>= 1) sv += __shfl_xor_sync(0xffffffffu, sv, o);
                __syncthreads();
                if (lane == 0) s_red[wid] = sv;
                __syncthreads();
                float tot = 0.f;
#pragma unroll
                for (int i = 0; i < 8; i++) tot += s_red[i];
                float inv = 1.f / tot;
                if (tid < PP) {
                    float al = ev * inv;
                    s_e[tid] = al;
                    wout[tid] = al;
                }
                __syncthreads();
                int hq = tid & 63, pc = tid >> 6;
                const float4* fb4 = (const float4*)(g_feats + (size_t)b * PP * HH);
                float4 a0 = make_float4(0,0,0,0), a1 = make_float4(0,0,0,0);
                for (int p = pc; p < PP; p += 4) {
                    float al = s_e[p];
                    float4 v0 = fb4[p*128 + hq*2];
                    float4 v1 = fb4[p*128 + hq*2 + 1];
                    a0.x = fmaf(al, v0.x, a0.x); a0.y = fmaf(al, v0.y, a0.y);
                    a0.z = fmaf(al, v0.z, a0.z); a0.w = fmaf(al, v0.w, a0.w);
                    a1.x = fmaf(al, v1.x, a1.x); a1.y = fmaf(al, v1.y, a1.y);
                    a1.z = fmaf(al, v1.z, a1.z); a1.w = fmaf(al, v1.w, a1.w);
                }
                float* rb = rbuf + pc*512 + hq*8;
                rb[0]=a0.x; rb[1]=a0.y; rb[2]=a0.z; rb[3]=a0.w;
                rb[4]=a1.x; rb[5]=a1.y; rb[6]=a1.z; rb[7]=a1.w;
                __syncthreads();
                for (int o = tid; o < 512; o += NTHR) {
                    float s = rbuf[o] + rbuf[512+o] + rbuf[1024+o] + rbuf[1536+o];
                    g_ctx[b*512 + o] = s;
                }
            }
        }
        gridbar(++nbar);

        // ---- Phase C: gates_ctx (mma) + combine + LSTM ----
        for (int pb = 0; pb < 2; pb++) {
            int b0 = pb*32;
            stage32(g_ctx, b0, smc + HT_OFF, tid);
            __syncthreads();
            gates_mma(smc + HT_OFF, smc + WIHC_OFF, part, wid, lane);
            __syncthreads();
            for (int o = tid; o < 512; o += NTHR) {
                int m = o >> 4, n = o & 15;
                int b = b0 + m;
                int gr = 512*(n >> 2) + j*4 + (n & 3);
                gh[b*16 + n] += part[o] + part[512 + o] + g_embg[(size_t)(b*TT + t)*NG + gr];
            }
            __syncthreads();
        }
        {
            int b = tid >> 2, q = tid & 3;
            float gi = gh[b*16 + q];
            float gf = gh[b*16 + 4 + q];
            float gg = gh[b*16 + 8 + q];
            float go = gh[b*16 + 12 + q];
            float ig = 1.f / (1.f + expf(-gi));
            float fg = 1.f / (1.f + expf(-gf));
            float gv = tanhf(gg);
            float og = 1.f / (1.f + expf(-go));
            int kc = j*4 + q;
            float c_new = fg * g_c[b*512 + kc] + ig * gv;
            float h_new = og * tanhf(c_new);
            g_hall[(size_t)(b*TT + t)*512 + kc] = h_new;
            if (t < sdl[b]) { g_h[b*512 + kc] = h_new; g_c[b*512 + kc] = c_new; }
        }
        gridbar(++nbar);
    }
}

// ======================= launch =======================
extern "C" void kernel_launch(void* const* d_in, const int* in_sizes, int n_in,
                              void* d_out, int out_size) {
    const float* imf     = (const float*)d_in[0];
    const int*   caps    = (const int*)  d_in[1];
    const int*   caplens = (const int*)  d_in[2];
    const float* emb     = (const float*)d_in[3];
    const float* W_ih    = (const float*)d_in[4];
    const float* W_hh    = (const float*)d_in[5];
    const float* b_ih    = (const float*)d_in[6];
    const float* b_hh    = (const float*)d_in[7];
    const float* W_enc   = (const float*)d_in[8];
    const float* b_enc   = (const float*)d_in[9];
    const float* W_dec   = (const float*)d_in[10];
    const float* b_dec   = (const float*)d_in[11];
    const float* W_full  = (const float*)d_in[12];
    const float* b_full  = (const float*)d_in[13];
    const float* W_score = (const float*)d_in[14];
    const float* b_score = (const float*)d_in[15];
    float* out = (float*)d_out;

    cudaFuncSetAttribute(k_recur, cudaFuncAttributeMaxDynamicSharedMemorySize, SM_TOTAL);

    // 1: sort + caps/declen/sortind outputs
    k_sort<<<1, BB>>>(caplens, caps, out);
    // 2: fused gathers + bf16 hi/lo conversions + zero scores + init h/c/bar
    k_cvt_all<<<1024, 256>>>(imf, caps, emb, W_enc, W_ih, W_score, out);
    // 3: fused enc_att + G_emb tensor-core GEMMs
    k_gemm_pair<<<792, 256>>>(b_enc, b_ih, b_hh);
    // 4: persistent recurrence (profiled slot)
    k_recur<<<NCTA, NTHR, SM_TOTAL>>>(W_dec, W_hh, W_ih, b_dec, W_full, b_full, out);
    // 5: h history conversion
    k_cvt_hall<<<(BB*TT*512 + 255)/256, 256>>>();
    // 6: scores GEMM
    k_gemm_scores<<<dim3((BB*TT + 127)/128, (VV + 127)/128), 256>>>(b_score, out);
}

// round 6
// speedup vs baseline: 1.5678x; 1.0670x over previous
#include <cuda_runtime.h>
#include <cuda_bf16.h>
#include <cstdint>
#include <math.h>

#define BB 64
#define PP 196
#define HH 512
#define EE 512
#define AA 512
#define VV 10000
#define MAXCAP 50
#define TT 49
#define NG 2048   // 4*H

// output layout (float32): scores (B,T,V), caps_s (B,50), decode_lengths (B,), weights (B,T,P), sort_ind (B,)
#define N_SCORES   (BB*TT*VV)
#define OFF_CAPS   (N_SCORES)
#define OFF_DECLEN (OFF_CAPS + BB*MAXCAP)
#define OFF_WEIGHTS (OFF_DECLEN + BB)
#define OFF_SORT   (OFF_WEIGHTS + BB*TT*PP)

#define NCTA 128
#define NTHR 256

// ======================= scratch =======================
__device__ float g_feats[BB*PP*HH];
__device__ float g_encatt[BB*PP*AA];
__device__ float g_embg[BB*TT*NG];
__device__ float g_hall[BB*TT*HH];
__device__ float g_h[BB*HH];
__device__ float g_c[BB*HH];
__device__ float g_att2[BB*AA];
__device__ float g_ctx[BB*HH];
__device__ int   g_sortidx[BB];
__device__ int   g_declen[BB];
__device__ int   g_nbact[TT];
__device__ int   g_act[BB*TT];
__device__ int   g_nact;
__device__ int   g_bars[160];

// bf16 hi/lo packed [rows][1024]: cols 0-511 hi, 512-1023 lo
__device__ __nv_bfloat16 g_feats2[BB*PP*1024];
__device__ __nv_bfloat16 g_embT2[BB*TT*1024];
__device__ __nv_bfloat16 g_hall2[BB*TT*1024];
__device__ __nv_bfloat16 g_Wenc2[AA*1024];
__device__ __nv_bfloat16 g_Wih2[NG*1024];
__device__ __nv_bfloat16 g_Wsc2[VV*1024];

// ======================= helpers =======================
__device__ __forceinline__ void mma16816(float* d, const uint32_t* a, const uint32_t* b) {
    asm volatile("mma.sync.aligned.m16n8k16.row.col.f32.bf16.bf16.f32 "
        "{%0,%1,%2,%3}, {%4,%5,%6,%7}, {%8,%9}, {%0,%1,%2,%3};"
        : "+f"(d[0]), "+f"(d[1]), "+f"(d[2]), "+f"(d[3])
        : "r"(a[0]), "r"(a[1]), "r"(a[2]), "r"(a[3]), "r"(b[0]), "r"(b[1]));
}
__device__ __forceinline__ void ldsm_x4(uint32_t* r, uint32_t saddr) {
    asm volatile("ldmatrix.sync.aligned.m8n8.x4.shared.b16 {%0,%1,%2,%3}, [%4];"
        : "=r"(r[0]), "=r"(r[1]), "=r"(r[2]), "=r"(r[3]) : "r"(saddr));
}
__device__ __forceinline__ void ldsm_x2(uint32_t* r, uint32_t saddr) {
    asm volatile("ldmatrix.sync.aligned.m8n8.x2.shared.b16 {%0,%1}, [%2];"
        : "=r"(r[0]), "=r"(r[1]) : "r"(saddr));
}
__device__ __forceinline__ uint32_t smem_u32(const void* p) {
    return (uint32_t)__cvta_generic_to_shared(p);
}
// store bf16x2 at (r, c even 0..31) in swizzled tile (64B rows, 16B-chunk XOR)
__device__ __forceinline__ void stsw2(char* s, int r, int c, uint32_t v) {
    int byte = r*64 + ((((c >> 3) ^ ((r >> 1) & 3))) << 4) + (c & 7)*2;
    *(uint32_t*)(s + byte) = v;
}
__device__ __forceinline__ void cvt_hilo2(float2 v, uint32_t& hp, uint32_t& lp) {
    __nv_bfloat16 h0 = __float2bfloat16(v.x), h1 = __float2bfloat16(v.y);
    float l0 = v.x - __bfloat162float(h0), l1 = v.y - __bfloat162float(h1);
    __nv_bfloat16 b0 = __float2bfloat16(l0), b1 = __float2bfloat16(l1);
    hp = (uint32_t)__bfloat16_as_ushort(h0) | ((uint32_t)__bfloat16_as_ushort(h1) << 16);
    lp = (uint32_t)__bfloat16_as_ushort(b0) | ((uint32_t)__bfloat16_as_ushort(b1) << 16);
}

// ======================= prep kernels =======================
__global__ void k_sort(const int* __restrict__ caplens, const int* __restrict__ caps,
                       float* __restrict__ out) {
    __shared__ int s_sort[BB];
    if (threadIdx.x == 0) {
        int cl[BB];
        for (int i = 0; i < BB; i++) cl[i] = caplens[i];
        int r = 0;
        for (int v = MAXCAP; v >= 0 && r < BB; v--)
            for (int i = 0; i < BB; i++)
                if (cl[i] == v) { g_sortidx[r] = i; s_sort[r] = i; r++; }
        int na = 0;
        int dls[BB];
        for (int b = 0; b < BB; b++) {
            int dl = cl[g_sortidx[b]] - 1;
            dls[b] = dl;
            g_declen[b] = dl;
            out[OFF_DECLEN + b] = (float)dl;
            out[OFF_SORT + b]   = (float)g_sortidx[b];
            for (int t = 0; t < dl; t++) g_act[na++] = b*TT + t;
        }
        g_nact = na;
        for (int t = 0; t < TT; t++) {
            int c = 0;
            for (int b = 0; b < BB; b++) if (dls[b] > t) c++;
            g_nbact[t] = c;
        }
    }
    __syncthreads();
    int b = threadIdx.x;
    int src = s_sort[b];
    for (int t = 0; t < MAXCAP; t++)
        out[OFF_CAPS + b*MAXCAP + t] = (float)caps[src*MAXCAP + t];
}

// fused gather + hi/lo conversion + zero + init
#define S0 (BB*PP*512)
#define S1 (BB*TT*512)
#define S2 (AA*512)
#define S3 (NG*512)
#define S4 (VV*512)
#define S5 (N_SCORES/4)
#define S6 (BB*TT*PP/4)
#define S7 (BB*HH)
__global__ void k_cvt_all(const float* __restrict__ imf, const int* __restrict__ caps,
                          const float* __restrict__ emb, const float* __restrict__ W_enc,
                          const float* __restrict__ W_ih, const float* __restrict__ W_score,
                          float* __restrict__ out)
{
    const int total = S0+S1+S2+S3+S4+S5+S6+S7+160;
    for (int i = blockIdx.x*blockDim.x + threadIdx.x; i < total; i += gridDim.x*blockDim.x) {
        int x = i;
        if (x < S0) {
            int row = x >> 9, c = x & 511;
            int b = row / PP, p = row - b*PP;
            float v = imf[((size_t)g_sortidx[b]*PP + p)*512 + c];
            g_feats[(size_t)row*512 + c] = v;
            __nv_bfloat16 hi = __float2bfloat16(v);
            g_feats2[(size_t)row*1024 + c] = hi;
            g_feats2[(size_t)row*1024 + 512 + c] = __float2bfloat16(v - __bfloat162float(hi));
            continue;
        }
        x -= S0;
        if (x < S1) {
            int row = x >> 9, c = x & 511;
            int b = row / TT, t = row - b*TT;
            int tok = caps[g_sortidx[b]*MAXCAP + t];
            float v = emb[(size_t)tok*512 + c];
            __nv_bfloat16 hi = __float2bfloat16(v);
            g_embT2[(size_t)row*1024 + c] = hi;
            g_embT2[(size_t)row*1024 + 512 + c] = __float2bfloat16(v - __bfloat162float(hi));
            continue;
        }
        x -= S1;
        if (x < S2) {
            int r = x >> 9, c = x & 511;
            float v = W_enc[x];
            __nv_bfloat16 hi = __float2bfloat16(v);
            g_Wenc2[(size_t)r*1024 + c] = hi;
            g_Wenc2[(size_t)r*1024 + 512 + c] = __float2bfloat16(v - __bfloat162float(hi));
            continue;
        }
        x -= S2;
        if (x < S3) {
            int r = x >> 9, c = x & 511;
            float v = W_ih[(size_t)r*1024 + c];
            __nv_bfloat16 hi = __float2bfloat16(v);
            g_Wih2[(size_t)r*1024 + c] = hi;
            g_Wih2[(size_t)r*1024 + 512 + c] = __float2bfloat16(v - __bfloat162float(hi));
            continue;
        }
        x -= S3;
        if (x < S4) {
            int r = x >> 9, c = x & 511;
            float v = W_score[x];
            __nv_bfloat16 hi = __float2bfloat16(v);
            g_Wsc2[(size_t)r*1024 + c] = hi;
            g_Wsc2[(size_t)r*1024 + 512 + c] = __float2bfloat16(v - __bfloat162float(hi));
            continue;
        }
        x -= S4;
        if (x < S5) {
            ((float4*)out)[x] = make_float4(0.f, 0.f, 0.f, 0.f);
            continue;
        }
        x -= S5;
        if (x < S6) {
            ((float4*)(out + OFF_WEIGHTS))[x] = make_float4(0.f, 0.f, 0.f, 0.f);
            continue;
        }
        x -= S6;
        if (x < S7) { g_h[x] = 0.f; g_c[x] = 0.f; continue; }
        x -= S7;
        g_bars[x] = 0;
    }
}

// ======================= mma.sync bf16x3 GEMM body (ldmatrix + double buffer) ==========
__device__ __forceinline__ void hgemm_body(
    int bm, int bn,
    const __nv_bfloat16* __restrict__ A2, const __nv_bfloat16* __restrict__ B2,
    int M, int N, int ldc,
    const float* __restrict__ bias1, const float* __restrict__ bias2,
    float* __restrict__ C, const int* __restrict__ rowmap, int use_nact,
    __nv_bfloat16 (*As)[128*32], __nv_bfloat16 (*Bs)[128*32])
{
    int tid = threadIdx.x;
    int Ml = use_nact ? g_nact : M;
    if (bm*128 >= Ml) return;

    int lrow = tid >> 1;
    int lc0 = (tid & 1) * 2;
    int gm = bm*128 + lrow;
    const uint4* arow = nullptr;
    if (gm < Ml) { int r = rowmap ? rowmap[gm] : gm; arow = (const uint4*)(A2 + (size_t)r*1024); }
    int gn = bn*128 + lrow;
    const uint4* brow = (gn < N) ? (const uint4*)(B2 + (size_t)gn*1024) : nullptr;

    int swz = (lrow >> 1) & 3;
    uint4* aswp[2] = {(uint4*)(As[0] + lrow*32), (uint4*)(As[1] + lrow*32)};
    uint4* bswp[2] = {(uint4*)(Bs[0] + lrow*32), (uint4*)(Bs[1] + lrow*32)};
    int c0 = lc0 ^ swz, c1 = (lc0+1) ^ swz;

    int lane = tid & 31, wid = tid >> 5;
    int wm = (wid >> 2) * 64;
    int wn = (wid & 3) * 32;
    int gq = lane >> 2, tg = lane & 3;

    // lane-constant fragment address parts
    int rA = wm + (lane & 15);
    int swzA = (rA >> 1) & 3;
    int hiA = lane >> 4;
    int rB = wn + (lane & 7);
    int swzB = (rB >> 1) & 3;
    int hiB = (lane >> 3) & 1;
    uint32_t aS[2] = {smem_u32(As[0]) + rA*64, smem_u32(As[1]) + rA*64};
    uint32_t bS[2] = {smem_u32(Bs[0]) + rB*64, smem_u32(Bs[1]) + rB*64};

    float acc[4][4][4];
#pragma unroll
    for (int mt = 0; mt < 4; mt++)
#pragma unroll
        for (int nt = 0; nt < 4; nt++)
#pragma unroll
            for (int r = 0; r < 4; r++) acc[mt][nt][r] = 0.f;

    const uint4 z = make_uint4(0,0,0,0);
    const int kau4[3] = {0, 0, 64};
    const int kbu4[3] = {0, 64, 0};
    uint4 pa0 = arow ? arow[lc0]   : z;
    uint4 pa1 = arow ? arow[lc0+1] : z;
    uint4 pb0 = brow ? brow[lc0]   : z;
    uint4 pb1 = brow ? brow[lc0+1] : z;
    aswp[0][c0] = pa0; aswp[0][c1] = pa1;
    bswp[0][c0] = pb0; bswp[0][c1] = pb1;
    __syncthreads();

    for (int ci = 0; ci < 48; ci++) {
        int cur = ci & 1;
        if (ci + 1 < 48) {
            int term = (ci+1) >> 4, kc = (ci+1) & 15;
            int ab = kau4[term] + kc*4, bb = kbu4[term] + kc*4;
            pa0 = arow ? arow[ab + lc0]   : z;
            pa1 = arow ? arow[ab + lc0+1] : z;
            pb0 = brow ? brow[bb + lc0]   : z;
            pb1 = brow ? brow[bb + lc0+1] : z;
        }
#pragma unroll
        for (int kk = 0; kk < 2; kk++) {
            uint32_t cA = (uint32_t)(((2*kk + hiA) ^ swzA) << 4);
            uint32_t cB = (uint32_t)(((2*kk + hiB) ^ swzB) << 4);
            uint32_t afr[4][4];
#pragma unroll
            for (int mt = 0; mt < 4; mt++)
                ldsm_x4(afr[mt], aS[cur] + mt*1024 + cA);
            uint32_t bfr[4][2];
#pragma unroll
            for (int nt = 0; nt < 4; nt++)
                ldsm_x2(bfr[nt], bS[cur] + nt*512 + cB);
#pragma unroll
            for (int mt = 0; mt < 4; mt++)
#pragma unroll
                for (int nt = 0; nt < 4; nt++)
                    mma16816(acc[mt][nt], afr[mt], bfr[nt]);
        }
        if (ci + 1 < 48) {
            int nxt = cur ^ 1;
            aswp[nxt][c0] = pa0; aswp[nxt][c1] = pa1;
            bswp[nxt][c0] = pb0; bswp[nxt][c1] = pb1;
        }
        __syncthreads();
    }

#pragma unroll
    for (int mt = 0; mt < 4; mt++) {
        int m0 = bm*128 + wm + mt*16 + gq;
        int m1 = m0 + 8;
        size_t row0 = 0, row1 = 0;
        bool v0 = m0 < Ml, v1 = m1 < Ml;
        if (v0) row0 = (size_t)(rowmap ? rowmap[m0] : m0);
        if (v1) row1 = (size_t)(rowmap ? rowmap[m1] : m1);
#pragma unroll
        for (int nt = 0; nt < 4; nt++) {
            int col = bn*128 + wn + nt*8 + tg*2;
            if (col >= N) continue;
            float bx = bias1[col], by = bias1[col+1];
            if (bias2) { bx += bias2[col]; by += bias2[col+1]; }
            if (v0) {
                float2 o = make_float2(acc[mt][nt][0] + bx, acc[mt][nt][1] + by);
                *(float2*)(C + row0*(size_t)ldc + col) = o;
            }
            if (v1) {
                float2 o = make_float2(acc[mt][nt][2] + bx, acc[mt][nt][3] + by);
                *(float2*)(C + row1*(size_t)ldc + col) = o;
            }
        }
    }
}

// fused launch: enc_att (98x4=392 blocks) + G_emb (25x16=400 blocks)
__global__ __launch_bounds__(256)
void k_gemm_pair(const float* __restrict__ b_enc, const float* __restrict__ b_ih,
                 const float* __restrict__ b_hh)
{
    __shared__ __align__(16) __nv_bfloat16 As[2][128*32];
    __shared__ __align__(16) __nv_bfloat16 Bs[2][128*32];
    int idx = blockIdx.x;
    if (idx < 392) {
        hgemm_body(idx >> 2, idx & 3, g_feats2, g_Wenc2, BB*PP, AA, AA,
                   b_enc, nullptr, g_encatt, nullptr, 0, As, Bs);
    } else {
        idx -= 392;
        hgemm_body(idx >> 4, idx & 15, g_embT2, g_Wih2, BB*TT, NG, NG,
                   b_ih, b_hh, g_embg, g_act, 1, As, Bs);
    }
}

__global__ __launch_bounds__(256)
void k_gemm_scores(const float* __restrict__ b_score, float* __restrict__ out)
{
    __shared__ __align__(16) __nv_bfloat16 As[2][128*32];
    __shared__ __align__(16) __nv_bfloat16 Bs[2][128*32];
    hgemm_body(blockIdx.x, blockIdx.y, g_hall2, g_Wsc2, BB*TT, VV, VV,
               b_score, nullptr, out, g_act, 1, As, Bs);
}

__global__ void k_cvt_hall() {
    int i = blockIdx.x*blockDim.x + threadIdx.x;
    if (i >= BB*TT*512) return;
    int r = i >> 9, c = i & 511;
    float v = g_hall[(size_t)r*512 + c];
    __nv_bfloat16 hi = __float2bfloat16(v);
    g_hall2[(size_t)r*1024 + c] = hi;
    g_hall2[(size_t)r*1024 + 512 + c] = __float2bfloat16(v - __bfloat162float(hi));
}

// ======================= fused persistent recurrence =======================
// smem byte offsets
#define WHH_OFF  0
#define WIHC_OFF 32768
#define WDEC_OFF 65536
#define HT_OFF   81920
#define PART_OFF 147456
#define GH_OFF   155648
#define SM_TOTAL 159744

__device__ __forceinline__ void gridbar(int slot) {
    __syncthreads();
    if (threadIdx.x == 0) {
        int* p = &g_bars[slot];
        asm volatile("red.release.gpu.global.add.s32 [%0], 1;" :: "l"(p) : "memory");
        int v;
        do {
            asm volatile("ld.acquire.gpu.global.s32 %0, [%1];" : "=r"(v) : "l"(p) : "memory");
        } while (v < NCTA);
    }
    __syncthreads();
}

// stage 32 rows (b0..b0+31) of fp32[512] into hi/lo swizzled tiles at HTp
__device__ __forceinline__ void stage32(const float* __restrict__ src, int b0, char* HTp, int tid) {
    for (int i = tid; i < 32*256; i += NTHR) {
        int r = i >> 8, kp = i & 255, k = kp*2;
        float2 v = *(const float2*)(src + (size_t)(b0+r)*512 + k);
        uint32_t hp, lp;
        cvt_hilo2(v, hp, lp);
        int kt = k >> 5, c = k & 31;
        stsw2(HTp + kt*2048, r, c, hp);
        stsw2(HTp + (16+kt)*2048, r, c, lp);
    }
}

// gates mma (ldmatrix): M=32, N=16, K=512, 3 hi/lo terms -> part[2][32][16]
__device__ __forceinline__ void gates_mma(uint32_t htA, uint32_t wbB, float* part,
                                          int wid, int lane) {
    int gq = lane >> 2, tg = lane & 3;
    int mh = (wid & 1)*16, nh = ((wid >> 1) & 1)*8, ks = wid >> 2;
    int rA = mh + (lane & 15);
    int swzA = (rA >> 1) & 3;
    int hiA = lane >> 4;
    int rB = nh + (lane & 7);
    int swzB = (rB >> 1) & 3;
    int hiB = (lane >> 3) & 1;
    uint32_t aL = htA + rA*64;
    uint32_t bL = wbB + rB*64;
    float acc[4] = {0.f, 0.f, 0.f, 0.f};
    for (int kt = ks*8; kt < ks*8 + 8; kt++) {
        uint32_t ah = aL + kt*2048;
        uint32_t bh = bL + kt*1024;
#pragma unroll
        for (int kk = 0; kk < 2; kk++) {
            uint32_t cA = (uint32_t)(((2*kk + hiA) ^ swzA) << 4);
            uint32_t cB = (uint32_t)(((2*kk + hiB) ^ swzB) << 4);
            uint32_t Ah[4], Al[4], Bh[2], Bl[2];
            ldsm_x4(Ah, ah + cA);
            ldsm_x4(Al, ah + 32768 + cA);
            ldsm_x2(Bh, bh + cB);
            ldsm_x2(Bl, bh + 16384 + cB);
            mma16816(acc, Ah, Bh);
            mma16816(acc, Ah, Bl);
            mma16816(acc, Al, Bh);
        }
    }
    int m0 = mh + gq, n0 = nh + tg*2;
    part[ks*512 + m0*16 + n0]       = acc[0];
    part[ks*512 + m0*16 + n0+1]     = acc[1];
    part[ks*512 + (m0+8)*16 + n0]   = acc[2];
    part[ks*512 + (m0+8)*16 + n0+1] = acc[3];
}

// att2 mma (ldmatrix): M=32, N=8 (4 real + 4 zero), K=512 -> part2[4][32][8]
__device__ __forceinline__ void att2_mma(uint32_t htA, uint32_t wdB, float* part2,
                                         int wid, int lane) {
    int gq = lane >> 2, tg = lane & 3;
    int mh = (wid & 1)*16, ks = wid >> 1;
    int rA = mh + (lane & 15);
    int swzA = (rA >> 1) & 3;
    int hiA = lane >> 4;
    int rB = lane & 7;
    int swzB = (rB >> 1) & 3;
    int hiB = (lane >> 3) & 1;
    uint32_t aL = htA + rA*64;
    uint32_t bL = wdB + rB*64;
    float acc[4] = {0.f, 0.f, 0.f, 0.f};
    for (int kt = ks*4; kt < ks*4 + 4; kt++) {
        uint32_t ah = aL + kt*2048;
        uint32_t bh = bL + kt*512;
#pragma unroll
        for (int kk = 0; kk < 2; kk++) {
            uint32_t cA = (uint32_t)(((2*kk + hiA) ^ swzA) << 4);
            uint32_t cB = (uint32_t)(((2*kk + hiB) ^ swzB) << 4);
            uint32_t Ah[4], Al[4], Bh[2], Bl[2];
            ldsm_x4(Ah, ah + cA);
            ldsm_x4(Al, ah + 32768 + cA);
            ldsm_x2(Bh, bh + cB);
            ldsm_x2(Bl, bh + 8192 + cB);
            mma16816(acc, Ah, Bh);
            mma16816(acc, Ah, Bl);
            mma16816(acc, Al, Bh);
        }
    }
    int m0 = mh + gq, n0 = tg*2;
    part2[ks*256 + m0*8 + n0]       = acc[0];
    part2[ks*256 + m0*8 + n0+1]     = acc[1];
    part2[ks*256 + (m0+8)*8 + n0]   = acc[2];
    part2[ks*256 + (m0+8)*8 + n0+1] = acc[3];
}

__global__ __launch_bounds__(NTHR)
void k_recur(const float* __restrict__ W_dec, const float* __restrict__ W_hh,
             const float* __restrict__ W_ih,
             const float* __restrict__ b_dec, const float* __restrict__ W_full,
             const float* __restrict__ b_full, float* __restrict__ out)
{
    extern __shared__ float sm[];
    char* smc = (char*)sm;
    __shared__ int sdl[BB];
    __shared__ int snb[TT];
    int tid = threadIdx.x, lane = tid & 31, wid = tid >> 5;
    int j = blockIdx.x;

    if (tid < BB) sdl[tid] = g_declen[tid];
    if (tid >= 64 && tid < 64 + TT) snb[tid - 64] = g_nbact[tid - 64];

    // convert weight slices to swizzled bf16 hi/lo tiles (once)
    for (int i = tid; i < 16*256; i += NTHR) {
        int r = i >> 8, kp = i & 255, k = kp*2;
        int gr = 512*(r >> 2) + j*4 + (r & 3);
        float2 w1 = *(const float2*)(W_hh + (size_t)gr*512 + k);
        float2 w2 = *(const float2*)(W_ih + (size_t)gr*1024 + 512 + k);
        uint32_t hp, lp;
        int kt = k >> 5, c = k & 31;
        cvt_hilo2(w1, hp, lp);
        stsw2(smc + WHH_OFF + kt*1024, r, c, hp);
        stsw2(smc + WHH_OFF + (16+kt)*1024, r, c, lp);
        cvt_hilo2(w2, hp, lp);
        stsw2(smc + WIHC_OFF + kt*1024, r, c, hp);
        stsw2(smc + WIHC_OFF + (16+kt)*1024, r, c, lp);
    }
    for (int i = tid; i < 8*256; i += NTHR) {
        int r = i >> 8, kp = i & 255, k = kp*2;
        float2 w = (r < 4) ? *(const float2*)(W_dec + (size_t)(j*4+r)*512 + k)
                           : make_float2(0.f, 0.f);
        uint32_t hp, lp;
        cvt_hilo2(w, hp, lp);
        int kt = k >> 5, c = k & 31;
        stsw2(smc + WDEC_OFF + kt*512, r, c, hp);
        stsw2(smc + WDEC_OFF + (16+kt)*512, r, c, lp);
    }
    __syncthreads();

    float* part  = (float*)(smc + PART_OFF);
    float* part2 = part + 1024;
    float* gh    = (float*)(smc + GH_OFF);
    uint32_t htS  = smem_u32(smc + HT_OFF);
    uint32_t whhS = smem_u32(smc + WHH_OFF);
    uint32_t wihS = smem_u32(smc + WIHC_OFF);
    uint32_t wdS  = smem_u32(smc + WDEC_OFF);

    int nbar = 0;
    for (int t = 0; t < TT; t++) {
        int npb = (snb[t] + 31) >> 5;
        // ---- Phase A: gates_h + att2 (mma) ----
        for (int pb = 0; pb < npb; pb++) {
            int b0 = pb*32;
            stage32(g_h, b0, smc + HT_OFF, tid);
            __syncthreads();
            gates_mma(htS, whhS, part, wid, lane);
            att2_mma(htS, wdS, part2, wid, lane);
            __syncthreads();
            for (int o = tid; o < 512; o += NTHR)
                gh[(b0 + (o >> 4))*16 + (o & 15)] = part[o] + part[512 + o];
            if (tid < 128) {
                int m = tid >> 2, q = tid & 3;
                float s = part2[m*8+q] + part2[256 + m*8+q] + part2[512 + m*8+q] + part2[768 + m*8+q];
                g_att2[(b0+m)*512 + j*4 + q] = s;
            }
            __syncthreads();
        }
        gridbar(nbar++);

        // ---- Phase B: attention (CTAs 0..63, active only) ----
        if (j < BB && t < sdl[j]) {
            int b = j;
            float* wout = out + OFF_WEIGHTS + (size_t)(b*TT + t)*PP;
            float* att = (float*)(smc + HT_OFF);
            float* s_att2 = att;
            float* s_wf   = att + 512;
            float* s_e    = att + 1024;
            float* s_red  = att + 1248;
            float* rbuf   = att + 1280;
            for (int a = tid; a < AA; a += NTHR) {
                s_att2[a] = g_att2[b*512 + a] + b_dec[a];
                s_wf[a] = W_full[a];
            }
            __syncthreads();
            const float* ea = g_encatt + (size_t)b * PP * AA;
            for (int p = wid; p < PP; p += 8) {
                const float* row = ea + (size_t)p * AA;
                float sum = 0.f;
                for (int a = lane; a < AA; a += 32)
                    sum += fmaxf(row[a] + s_att2[a], 0.f) * s_wf[a];
#pragma unroll
                for (int o = 16; o; o >>= 1) sum += __shfl_xor_sync(0xffffffffu, sum, o);
                if (lane == 0) s_e[p] = sum + b_full[0];
            }
            __syncthreads();
            float m = -1e30f;
            if (tid < PP) m = s_e[tid];
#pragma unroll
            for (int o = 16; o; o >>= 1) m = fmaxf(m, __shfl_xor_sync(0xffffffffu, m, o));
            if (lane == 0) s_red[wid] = m;
            __syncthreads();
            float mx = s_red[0];
#pragma unroll
            for (int i = 1; i < 8; i++) mx = fmaxf(mx, s_red[i]);
            float ev = 0.f;
            if (tid < PP) ev = expf(s_e[tid] - mx);
            float sv = ev;
#pragma unroll
            for (int o = 16; o; o >>= 1) sv += __shfl_xor_sync(0xffffffffu, sv, o);
            __syncthreads();
            if (lane == 0) s_red[wid] = sv;
            __syncthreads();
            float tot = 0.f;
#pragma unroll
            for (int i = 0; i < 8; i++) tot += s_red[i];
            float inv = 1.f / tot;
            if (tid < PP) {
                float al = ev * inv;
                s_e[tid] = al;
                wout[tid] = al;
            }
            __syncthreads();
            int hq = tid & 63, pc = tid >> 6;
            const float4* fb4 = (const float4*)(g_feats + (size_t)b * PP * HH);
            float4 a0 = make_float4(0,0,0,0), a1 = make_float4(0,0,0,0);
            for (int p = pc; p < PP; p += 4) {
                float al = s_e[p];
                float4 v0 = fb4[p*128 + hq*2];
                float4 v1 = fb4[p*128 + hq*2 + 1];
                a0.x = fmaf(al, v0.x, a0.x); a0.y = fmaf(al, v0.y, a0.y);
                a0.z = fmaf(al, v0.z, a0.z); a0.w = fmaf(al, v0.w, a0.w);
                a1.x = fmaf(al, v1.x, a1.x); a1.y = fmaf(al, v1.y, a1.y);
                a1.z = fmaf(al, v1.z, a1.z); a1.w = fmaf(al, v1.w, a1.w);
            }
            float* rb = rbuf + pc*512 + hq*8;
            rb[0]=a0.x; rb[1]=a0.y; rb[2]=a0.z; rb[3]=a0.w;
            rb[4]=a1.x; rb[5]=a1.y; rb[6]=a1.z; rb[7]=a1.w;
            __syncthreads();
            for (int o = tid; o < 512; o += NTHR) {
                float s = rbuf[o] + rbuf[512+o] + rbuf[1024+o] + rbuf[1536+o];
                g_ctx[b*512 + o] = s;
            }
        }
        gridbar(nbar++);

        // ---- Phase C: gates_ctx (mma) + combine + LSTM ----
        for (int pb = 0; pb < npb; pb++) {
            int b0 = pb*32;
            stage32(g_ctx, b0, smc + HT_OFF, tid);
            __syncthreads();
            gates_mma(htS, wihS, part, wid, lane);
            __syncthreads();
            for (int o = tid; o < 512; o += NTHR) {
                int m = o >> 4, n = o & 15;
                int b = b0 + m;
                int gr = 512*(n >> 2) + j*4 + (n & 3);
                gh[b*16 + n] += part[o] + part[512 + o] + g_embg[(size_t)(b*TT + t)*NG + gr];
            }
            __syncthreads();
        }
        {
            int b = tid >> 2, q = tid & 3;
            if (t < sdl[b]) {
                float gi = gh[b*16 + q];
                float gf = gh[b*16 + 4 + q];
                float gg = gh[b*16 + 8 + q];
                float go = gh[b*16 + 12 + q];
                float ig = 1.f / (1.f + expf(-gi));
                float fg = 1.f / (1.f + expf(-gf));
                float gv = tanhf(gg);
                float og = 1.f / (1.f + expf(-go));
                int kc = j*4 + q;
                float c_new = fg * g_c[b*512 + kc] + ig * gv;
                float h_new = og * tanhf(c_new);
                g_hall[(size_t)(b*TT + t)*512 + kc] = h_new;
                g_h[b*512 + kc] = h_new;
                g_c[b*512 + kc] = c_new;
            }
        }
        gridbar(nbar++);
    }
}

// ======================= launch =======================
extern "C" void kernel_launch(void* const* d_in, const int* in_sizes, int n_in,
                              void* d_out, int out_size) {
    const float* imf     = (const float*)d_in[0];
    const int*   caps    = (const int*)  d_in[1];
    const int*   caplens = (const int*)  d_in[2];
    const float* emb     = (const float*)d_in[3];
    const float* W_ih    = (const float*)d_in[4];
    const float* W_hh    = (const float*)d_in[5];
    const float* b_ih    = (const float*)d_in[6];
    const float* b_hh    = (const float*)d_in[7];
    const float* W_enc   = (const float*)d_in[8];
    const float* b_enc   = (const float*)d_in[9];
    const float* W_dec   = (const float*)d_in[10];
    const float* b_dec   = (const float*)d_in[11];
    const float* W_full  = (const float*)d_in[12];
    const float* b_full  = (const float*)d_in[13];
    const float* W_score = (const float*)d_in[14];
    const float* b_score = (const float*)d_in[15];
    float* out = (float*)d_out;

    cudaFuncSetAttribute(k_recur, cudaFuncAttributeMaxDynamicSharedMemorySize, SM_TOTAL);

    // 1: sort + caps/declen/sortind outputs
    k_sort<<<1, BB>>>(caplens, caps, out);
    // 2: fused gathers + bf16 hi/lo conversions + zeroing + init
    k_cvt_all<<<1024, 256>>>(imf, caps, emb, W_enc, W_ih, W_score, out);
    // 3: fused enc_att + G_emb tensor-core GEMMs
    k_gemm_pair<<<792, 256>>>(b_enc, b_ih, b_hh);
    // 4: persistent recurrence
    k_recur<<<NCTA, NTHR, SM_TOTAL>>>(W_dec, W_hh, W_ih, b_dec, W_full, b_full, out);
    // 5: h history conversion
    k_cvt_hall<<<(BB*TT*512 + 255)/256, 256>>>();
    // 6: scores GEMM
    k_gemm_scores<<<dim3((BB*TT + 127)/128, (VV + 127)/128), 256>>>(b_score, out);
}